// round 13
// baseline (speedup 1.0000x reference)
#include <cuda_runtime.h>
#include <cuda_fp16.h>
#include <cstdint>

// Problem dims
#define B_  4
#define S_  2048
#define DM_ 2048
#define H_  16
#define HD_ 128
#define SCALE_ 0.08838834764831843f   // 1/sqrt(128)

typedef __half h16;

// ---------------- scratch (__device__ globals) ----------------
__device__ h16 g_xh[(size_t)B_ * S_ * DM_];       // single fp16
__device__ h16 g_Qh[(size_t)B_ * S_ * DM_];
__device__ h16 g_Kh[(size_t)B_ * S_ * HD_];
__device__ h16 g_Vth[(size_t)B_ * HD_ * S_];      // [B][128][2048]
__device__ h16 g_attnh[(size_t)B_ * S_ * DM_];
__device__ h16 g_Wqh[(size_t)DM_ * DM_];          // transposed [N][K]
__device__ h16 g_Wkh[(size_t)HD_ * DM_];
__device__ h16 g_Wvh[(size_t)HD_ * DM_];
__device__ h16 g_Woh[(size_t)DM_ * DM_];
__device__ float g_rowsum[(size_t)B_ * H_ * S_];

// ---------------- smem layouts ----------------
// BK=64 cores: 3-stage ring; stage = {A, B}, each 128 x 72 fp16 = 18432 B
#define LDT64   72
#define TILE64  (128 * LDT64 * 2)         // 18432
#define STAGE64 (2 * TILE64)              // 36864
#define AUX64   (3 * STAGE64)             // 110592 (staging 67584 unions below)
#define RED64   (AUX64 + 512)
#define SMEM64  (AUX64 + 1536)            // 112128
// BK=32 PV core: 3-stage ring; stage = {A, B}, each 128 x 40 fp16 = 10240 B
#define LDT32   40
#define TILE32  10240
#define STAGE32 (2 * TILE32)              // 20480; x3 = 61440
#define AUX32   67584                     // after fp32 staging 128x132x4
#define SMEM32  69632

// ---------------- low-level helpers ----------------
__device__ __forceinline__ uint32_t smem_u32(const void* p) {
    uint32_t a;
    asm("{ .reg .u64 t; cvta.to.shared.u64 t, %1; cvt.u32.u64 %0, t; }" : "=r"(a) : "l"(p));
    return a;
}
__device__ __forceinline__ void cp16(uint32_t s, const void* g) {
    asm volatile("cp.async.ca.shared.global [%0], [%1], 16;"
                 :: "r"(s), "l"(__cvta_generic_to_global(g)));
}
#define CP_COMMIT() asm volatile("cp.async.commit_group;" ::: "memory")
#define CP_WAIT1()  asm volatile("cp.async.wait_group 1;" ::: "memory")
__device__ __forceinline__ void ldsm4(uint32_t* r, uint32_t a) {
    asm volatile("ldmatrix.sync.aligned.m8n8.x4.shared.b16 {%0,%1,%2,%3}, [%4];"
        : "=r"(r[0]), "=r"(r[1]), "=r"(r[2]), "=r"(r[3]) : "r"(a));
}
__device__ __forceinline__ void mma_fp16(float* d, const uint32_t* a, uint32_t b0, uint32_t b1) {
    asm volatile("mma.sync.aligned.m16n8k16.row.col.f32.f16.f16.f32 "
        "{%0,%1,%2,%3}, {%4,%5,%6,%7}, {%8,%9}, {%0,%1,%2,%3};"
        : "+f"(d[0]), "+f"(d[1]), "+f"(d[2]), "+f"(d[3])
        : "r"(a[0]), "r"(a[1]), "r"(a[2]), "r"(a[3]), "r"(b0), "r"(b1));
}
__device__ __forceinline__ uint32_t hbits2(__half2 h) {
    return *reinterpret_cast<uint32_t*>(&h);
}
__device__ __forceinline__ void pack4h(float4 v, uint32_t& h0, uint32_t& h1) {
    __half2 a = __floats2half2_rn(v.x, v.y);
    __half2 b = __floats2half2_rn(v.z, v.w);
    h0 = hbits2(a); h1 = hbits2(b);
}

// ---------------- BK=64 tile movement ----------------
__device__ __forceinline__ void issue_tiles64(char* buf,
    const h16* __restrict__ Ag, size_t lda,
    const h16* __restrict__ Bg, size_t ldb,
    int k0, int tid)
{
    uint32_t sA = smem_u32(buf);
#pragma unroll
    for (int i = 0; i < 4; i++) {
        int idx = i * 256 + tid;              // 0..1023
        int r = idx >> 3, c8 = (idx & 7) * 8;
        cp16(sA + r * (LDT64 * 2) + c8 * 2, Ag + (size_t)r * lda + k0 + c8);
    }
    uint32_t sB = sA + TILE64;
#pragma unroll
    for (int i = 0; i < 4; i++) {
        int idx = i * 256 + tid;
        int r = idx >> 3, c8 = (idx & 7) * 8;
        cp16(sB + r * (LDT64 * 2) + c8 * 2, Bg + (size_t)r * ldb + k0 + c8);
    }
}
// BK=32 B-only (PV)
__device__ __forceinline__ void issue_B32(char* buf,
    const h16* __restrict__ Bg, size_t ldb, int k0, int tid)
{
    uint32_t sB = smem_u32(buf) + TILE32;
#pragma unroll
    for (int i = 0; i < 2; i++) {
        int idx = i * 256 + tid;
        int r = idx >> 2, c8 = (idx & 3) * 8;
        cp16(sB + r * (LDT32 * 2) + c8 * 2, Bg + (size_t)r * ldb + k0 + c8);
    }
}

// ---------------- MMA compute: one chunk, warp 32x64, 1-term ----------------
template<int LDT, int TILE, int BK>
__device__ __forceinline__ void compute_chunk(float (*acc)[8][4], char* buf,
                                              int wm, int wn, int lane)
{
    h16* Ah = (h16*)buf;
    h16* Bh = (h16*)(buf + TILE);
    const int ar = lane & 15;
    const int acs = (lane >> 4) << 3;
#pragma unroll
    for (int kk = 0; kk < BK; kk += 16) {
        const int ac = kk + acs;
        uint32_t aH[2][4];
#pragma unroll
        for (int mt = 0; mt < 2; mt++)
            ldsm4(aH[mt], smem_u32(Ah + (wm * 32 + mt * 16 + ar) * LDT + ac));
#pragma unroll
        for (int p = 0; p < 4; p++) {
            uint32_t bh[4];
            ldsm4(bh, smem_u32(Bh + (wn * 64 + p * 16 + ar) * LDT + ac));
#pragma unroll
            for (int mt = 0; mt < 2; mt++) {
                mma_fp16(acc[mt][2 * p],     aH[mt], bh[0], bh[2]);
                mma_fp16(acc[mt][2 * p + 1], aH[mt], bh[1], bh[3]);
            }
        }
    }
}

// BK=64 pipelined core: 3-stage ring, ONE sync per chunk
__device__ __forceinline__ void gemm_core_h(float (*acc)[8][4],
    const h16* __restrict__ Ag, size_t lda,
    const h16* __restrict__ Bg, size_t ldb,
    int Kdim, char* smem)
{
    const int tid = threadIdx.x, wid = tid >> 5, lane = tid & 31;
    const int wm = wid & 3, wn = wid >> 2;
    const int nC = Kdim >> 6;
    issue_tiles64(smem, Ag, lda, Bg, ldb, 0, tid); CP_COMMIT();
    if (nC > 1) issue_tiles64(smem + STAGE64, Ag, lda, Bg, ldb, 64, tid);
    CP_COMMIT();
#pragma unroll 1
    for (int c = 0; c < nC; c++) {
        CP_WAIT1();
        __syncthreads();                       // chunk c ready; buf (c+2)%3 freed
        if (c + 2 < nC)
            issue_tiles64(smem + ((c + 2) % 3) * STAGE64, Ag, lda, Bg, ldb,
                          (c + 2) * 64, tid);
        CP_COMMIT();
        compute_chunk<LDT64, TILE64, 64>(acc, smem + (c % 3) * STAGE64, wm, wn, lane);
    }
    asm volatile("cp.async.wait_all;" ::: "memory");
    __syncthreads();
}

// PV core: BK=32, 3-stage ring, one sync. A = fp32 scores with register
// double-buffer prefetch: normalize by rinv, write back, pack fp16 to smem.
__device__ __forceinline__ void gemm_core_pv(float (*acc)[8][4],
    float* __restrict__ A, size_t lda,
    const h16* __restrict__ Bg, size_t ldb,
    int Kdim, char* smem, const float* __restrict__ rinv)
{
    const int tid = threadIdx.x, wid = tid >> 5, lane = tid & 31;
    const int wm = wid & 3, wn = wid >> 2;
    const int nC = Kdim >> 5;                     // 64
    issue_B32(smem, Bg, ldb, 0, tid); CP_COMMIT();
    issue_B32(smem + STAGE32, Bg, ldb, 32, tid); CP_COMMIT();

    float4 pr[4];
#pragma unroll
    for (int i = 0; i < 4; i++) {
        int idx = i * 256 + tid;
        int rr = idx >> 3, cc = (idx & 7) * 4;
        pr[i] = *(const float4*)(A + (size_t)rr * lda + cc);
    }
#pragma unroll 1
    for (int c = 0; c < nC; c++) {
        char* buf = smem + (c % 3) * STAGE32;
        CP_WAIT1();
        // fill A chunk c into buf c%3 (freed 2 iterations ago)
        h16* Ah = (h16*)buf;
#pragma unroll
        for (int i = 0; i < 4; i++) {
            int idx = i * 256 + tid;
            int rr = idx >> 3, cc = (idx & 7) * 4;
            float ri = rinv[rr];
            float4 v = pr[i];
            v.x *= ri; v.y *= ri; v.z *= ri; v.w *= ri;
            *(float4*)(A + (size_t)rr * lda + c * 32 + cc) = v;
            uint32_t h0, h1; pack4h(v, h0, h1);
            *(uint2*)(Ah + rr * LDT32 + cc) = make_uint2(h0, h1);
        }
        if (c + 1 < nC) {
#pragma unroll
            for (int i = 0; i < 4; i++) {
                int idx = i * 256 + tid;
                int rr = idx >> 3, cc = (idx & 7) * 4;
                pr[i] = *(const float4*)(A + (size_t)rr * lda + (c + 1) * 32 + cc);
            }
        }
        __syncthreads();                       // A(c) visible; B(c) ready; buf (c+2)%3 freed
        if (c + 2 < nC)
            issue_B32(smem + ((c + 2) % 3) * STAGE32, Bg, ldb, (c + 2) * 32, tid);
        CP_COMMIT();
        compute_chunk<LDT32, TILE32, 32>(acc, buf, wm, wn, lane);
    }
    asm volatile("cp.async.wait_all;" ::: "memory");
    __syncthreads();
}

// stage acc (fp32) into smem [128][132]
__device__ __forceinline__ void stage_acc(float (*acc)[8][4], float* stg, int wid, int lane) {
    int wm = wid & 3, wn = wid >> 2;
    int r0 = wm * 32 + (lane >> 2), c0 = wn * 64 + (lane & 3) * 2;
#pragma unroll
    for (int mt = 0; mt < 2; mt++)
#pragma unroll
        for (int nt = 0; nt < 8; nt++) {
            int r = r0 + mt * 16, c = c0 + nt * 8;
            *(float2*)&stg[r * 132 + c] = make_float2(acc[mt][nt][0], acc[mt][nt][1]);
            *(float2*)&stg[(r + 8) * 132 + c] = make_float2(acc[mt][nt][2], acc[mt][nt][3]);
        }
}

#define ZERO_ACC(acc) \
    _Pragma("unroll") for (int i_ = 0; i_ < 2; i_++) \
    _Pragma("unroll") for (int j_ = 0; j_ < 8; j_++) \
    _Pragma("unroll") for (int q_ = 0; q_ < 4; q_++) acc[i_][j_][q_] = 0.0f;

// ---------------- prep kernels ----------------
__global__ void split_x_kernel(const float* __restrict__ x, h16* __restrict__ xh, int n4) {
    int i = blockIdx.x * blockDim.x + threadIdx.x;
    if (i >= n4) return;
    float4 v = *(const float4*)(x + 4 * (size_t)i);
    uint32_t h0, h1; pack4h(v, h0, h1);
    *(uint2*)(xh + 4 * (size_t)i) = make_uint2(h0, h1);
}
__global__ void transpose_pack_kernel(const float* __restrict__ src,
                                      h16* __restrict__ dh, int M, int N) {
    __shared__ float t[32][33];
    int bx = blockIdx.x * 32, by = blockIdx.y * 32;
    int x = threadIdx.x, y0 = threadIdx.y;
#pragma unroll
    for (int j = 0; j < 32; j += 8)
        t[y0 + j][x] = src[(size_t)(by + y0 + j) * N + bx + x];
    __syncthreads();
#pragma unroll
    for (int j = 0; j < 32; j += 8)
        dh[(size_t)(bx + y0 + j) * M + by + x] = __float2half_rn(t[x][y0 + j]);
}
__global__ void zero_kernel(float* p, int n) {
    int i = blockIdx.x * blockDim.x + threadIdx.x;
    if (i < n) p[i] = 0.0f;
}

// ---------------- fused Q + K + V projection ----------------
// grid (18, 64): x<16 -> Q col tile x; x==16 -> K; x==17 -> V
__global__ __launch_bounds__(256, 2) void mma_qkvproj(
    const h16* __restrict__ Ag,
    const h16* __restrict__ Wqh, const h16* __restrict__ Wkh, const h16* __restrict__ Wvh,
    const float* __restrict__ bq, const float* __restrict__ bk, const float* __restrict__ bv,
    h16* __restrict__ Qh, h16* __restrict__ Kh, h16* __restrict__ Vth)
{
    extern __shared__ __align__(16) char smem[];
    const int tid = threadIdx.x, wid = tid >> 5, lane = tid & 31;
    const int bx = blockIdx.x;
    const int row0 = blockIdx.y * 128;

    const h16* Bg;
    const float* bias;
    if (bx < 16)      { Bg = Wqh + (size_t)bx * 128 * DM_; bias = bq + bx * 128; }
    else if (bx == 16){ Bg = Wkh; bias = bk; }
    else              { Bg = Wvh; bias = bv; }

    float* bs = (float*)(smem + AUX64);
    if (tid < 128) bs[tid] = bias[tid];

    float acc[2][8][4];
    ZERO_ACC(acc)
    gemm_core_h(acc, Ag + (size_t)row0 * DM_, DM_, Bg, DM_, DM_, smem);

    float* stg = (float*)smem;
    stage_acc(acc, stg, wid, lane);
    __syncthreads();
    if (bx < 16) {
        // Q: single fp16 [B*S, DM], col block bx*128
#pragma unroll 1
        for (int i = 0; i < 16; i++) {
            int idx = i * 256 + tid;
            int rr = idx >> 5, c4 = (idx & 31) << 2;
            float4 v = *(float4*)&stg[rr * 132 + c4];
            v.x += bs[c4]; v.y += bs[c4 + 1]; v.z += bs[c4 + 2]; v.w += bs[c4 + 3];
            uint32_t h0, h1; pack4h(v, h0, h1);
            *(uint2*)(Qh + (size_t)(row0 + rr) * DM_ + bx * 128 + c4) = make_uint2(h0, h1);
        }
    } else if (bx == 16) {
        // K: single fp16, row-major [B*S, HD]
#pragma unroll 1
        for (int i = 0; i < 16; i++) {
            int idx = i * 256 + tid;
            int rr = idx >> 5, c4 = (idx & 31) << 2;
            float4 v = *(float4*)&stg[rr * 132 + c4];
            v.x += bs[c4]; v.y += bs[c4 + 1]; v.z += bs[c4 + 2]; v.w += bs[c4 + 3];
            uint32_t h0, h1; pack4h(v, h0, h1);
            *(uint2*)(Kh + (size_t)(row0 + rr) * HD_ + c4) = make_uint2(h0, h1);
        }
    } else {
        // V: single fp16, transposed [B][HD][S]
        int b = row0 >> 11;
        int s0 = row0 & (S_ - 1);
        h16* Vb = Vth + (size_t)b * HD_ * S_;
#pragma unroll 1
        for (int i = 0; i < 64; i++) {
            int idx = i * 256 + tid;
            int m = idx & 127, n = idx >> 7;
            Vb[(size_t)n * S_ + s0 + m] = __float2half_rn(stg[m * 132 + n] + bs[n]);
        }
    }
}

// ---------------- scores: E = exp(scale * Q Kt) fp32 out + rowsums ----------------
__global__ __launch_bounds__(256, 2) void mma_scores(
    const h16* __restrict__ Qh,
    const h16* __restrict__ Kh,
    float* __restrict__ scores, float* __restrict__ rowsum)
{
    extern __shared__ __align__(16) char smem[];
    const int tid = threadIdx.x, wid = tid >> 5, lane = tid & 31;
    const int bh = blockIdx.z;
    const int b = bh >> 4, hd = bh & 15;
    const int row0 = blockIdx.y * 128, col0 = blockIdx.x * 128;

    float acc[2][8][4];
    ZERO_ACC(acc)
    gemm_core_h(acc,
        Qh + ((size_t)b * S_ + row0) * DM_ + hd * HD_, DM_,
        Kh + ((size_t)b * S_ + col0) * HD_, HD_, HD_, smem);

    float* stg = (float*)smem;
    float* red = (float*)(smem + RED64);
    const int wm = wid & 3, wn = wid >> 2;
    const int r0 = wm * 32 + (lane >> 2), c0 = wn * 64 + (lane & 3) * 2;
    float sums[2][2] = {{0.f, 0.f}, {0.f, 0.f}};
#pragma unroll
    for (int mt = 0; mt < 2; mt++)
#pragma unroll
        for (int nt = 0; nt < 8; nt++) {
            float e0 = __expf(acc[mt][nt][0] * SCALE_);
            float e1 = __expf(acc[mt][nt][1] * SCALE_);
            float e2 = __expf(acc[mt][nt][2] * SCALE_);
            float e3 = __expf(acc[mt][nt][3] * SCALE_);
            int r = r0 + mt * 16, c = c0 + nt * 8;
            *(float2*)&stg[r * 132 + c] = make_float2(e0, e1);
            *(float2*)&stg[(r + 8) * 132 + c] = make_float2(e2, e3);
            sums[mt][0] += e0 + e1;
            sums[mt][1] += e2 + e3;
        }
#pragma unroll
    for (int mt = 0; mt < 2; mt++)
#pragma unroll
        for (int hh = 0; hh < 2; hh++) {
            float v = sums[mt][hh];
            v += __shfl_xor_sync(0xFFFFFFFFu, v, 1);
            v += __shfl_xor_sync(0xFFFFFFFFu, v, 2);
            sums[mt][hh] = v;
        }
    if ((lane & 3) == 0) {
#pragma unroll
        for (int mt = 0; mt < 2; mt++)
#pragma unroll
            for (int hh = 0; hh < 2; hh++)
                red[(wm * 32 + mt * 16 + hh * 8 + (lane >> 2)) * 2 + wn] = sums[mt][hh];
    }
    __syncthreads();
    if (tid < 128)
        atomicAdd(&rowsum[(size_t)bh * S_ + row0 + tid], red[tid * 2] + red[tid * 2 + 1]);

    float* Crow = scores + ((size_t)bh * S_ + row0) * S_ + col0;
#pragma unroll 1
    for (int i = 0; i < 16; i++) {
        int idx = i * 256 + tid;
        int rr = idx >> 5, c4 = (idx & 31) << 2;
        *(float4*)&Crow[(size_t)rr * S_ + c4] = *(float4*)&stg[rr * 132 + c4];
    }
}

// ---------------- normalize scores in place + PV (single-fp16 epilogue) ----------------
__global__ __launch_bounds__(256, 2) void mma_softmax_pv(
    float* __restrict__ scores, const float* __restrict__ rowsum,
    const h16* __restrict__ Vth, h16* __restrict__ attnh)
{
    extern __shared__ __align__(16) char smem[];
    const int tid = threadIdx.x, wid = tid >> 5, lane = tid & 31;
    const int bh = blockIdx.y;
    const int b = bh >> 4, hd = bh & 15;
    const int row0 = blockIdx.x * 128;

    float* rinv = (float*)(smem + AUX32);
    if (tid < 128) rinv[tid] = 1.0f / rowsum[(size_t)bh * S_ + row0 + tid];
    __syncthreads();

    float acc[2][8][4];
    ZERO_ACC(acc)
    gemm_core_pv(acc, scores + ((size_t)bh * S_ + row0) * S_, S_,
                 Vth + (size_t)b * HD_ * S_, S_, S_, smem, rinv);

    float* stg = (float*)smem;
    stage_acc(acc, stg, wid, lane);
    __syncthreads();
    h16* Cb = attnh + ((size_t)b * S_ + row0) * DM_ + hd * HD_;
#pragma unroll 1
    for (int i = 0; i < 16; i++) {
        int idx = i * 256 + tid;
        int rr = idx >> 5, c4 = (idx & 31) << 2;
        float4 v = *(float4*)&stg[rr * 132 + c4];
        uint32_t h0, h1; pack4h(v, h0, h1);
        *(uint2*)(Cb + (size_t)rr * DM_ + c4) = make_uint2(h0, h1);
    }
}

// ---------------- output GEMM (fp32 + bias epilogue) ----------------
__global__ __launch_bounds__(256, 2) void mma_out(
    const h16* __restrict__ Ag,
    const h16* __restrict__ Bg,
    const float* __restrict__ bias, float* __restrict__ C)
{
    extern __shared__ __align__(16) char smem[];
    const int tid = threadIdx.x, wid = tid >> 5, lane = tid & 31;
    const int row0 = blockIdx.y * 128, col0 = blockIdx.x * 128;

    float* bs = (float*)(smem + AUX64);
    if (tid < 128) bs[tid] = bias[col0 + tid];

    float acc[2][8][4];
    ZERO_ACC(acc)
    gemm_core_h(acc, Ag + (size_t)row0 * DM_, DM_,
                Bg + (size_t)col0 * DM_, DM_, DM_, smem);

    float* stg = (float*)smem;
    stage_acc(acc, stg, wid, lane);
    __syncthreads();
#pragma unroll 1
    for (int i = 0; i < 16; i++) {
        int idx = i * 256 + tid;
        int rr = idx >> 5, c4 = (idx & 31) << 2;
        float4 v = *(float4*)&stg[rr * 132 + c4];
        v.x += bs[c4]; v.y += bs[c4 + 1]; v.z += bs[c4 + 2]; v.w += bs[c4 + 3];
        *(float4*)&C[(size_t)(row0 + rr) * DM_ + col0 + c4] = v;
    }
}

// ---------------- launch ----------------
extern "C" void kernel_launch(void* const* d_in, const int* in_sizes, int n_in,
                              void* d_out, int out_size)
{
    const float* x  = (const float*)d_in[0];
    const float* Wq = (const float*)d_in[1];
    const float* bq = (const float*)d_in[2];
    const float* Wk = (const float*)d_in[3];
    const float* bk = (const float*)d_in[4];
    const float* Wv = (const float*)d_in[5];
    const float* bv = (const float*)d_in[6];
    const float* Wo = (const float*)d_in[7];
    const float* bo = (const float*)d_in[8];

    float* out = (float*)d_out;
    float* scores = out + (size_t)B_ * S_ * DM_;

    h16 *pxh, *pQh, *pKh, *pVth, *pAh;
    h16 *pWqh, *pWkh, *pWvh, *pWoh;
    float* pRS;
    cudaGetSymbolAddress((void**)&pxh, g_xh);
    cudaGetSymbolAddress((void**)&pQh, g_Qh);
    cudaGetSymbolAddress((void**)&pKh, g_Kh);
    cudaGetSymbolAddress((void**)&pVth, g_Vth);
    cudaGetSymbolAddress((void**)&pAh, g_attnh);
    cudaGetSymbolAddress((void**)&pWqh, g_Wqh);
    cudaGetSymbolAddress((void**)&pWkh, g_Wkh);
    cudaGetSymbolAddress((void**)&pWvh, g_Wvh);
    cudaGetSymbolAddress((void**)&pWoh, g_Woh);
    cudaGetSymbolAddress((void**)&pRS, g_rowsum);

    static int smem_set = 0;
    if (!smem_set) {
        cudaFuncSetAttribute(mma_qkvproj, cudaFuncAttributeMaxDynamicSharedMemorySize, SMEM64);
        cudaFuncSetAttribute(mma_scores, cudaFuncAttributeMaxDynamicSharedMemorySize, SMEM64);
        cudaFuncSetAttribute(mma_softmax_pv, cudaFuncAttributeMaxDynamicSharedMemorySize, SMEM32);
        cudaFuncSetAttribute(mma_out, cudaFuncAttributeMaxDynamicSharedMemorySize, SMEM64);
        smem_set = 1;
    }

    const int M = B_ * S_;   // 8192
    split_x_kernel<<<(M * DM_ / 4 + 255) / 256, 256>>>(x, pxh, M * DM_ / 4);
    transpose_pack_kernel<<<dim3(DM_ / 32, DM_ / 32), dim3(32, 8)>>>(Wq, pWqh, DM_, DM_);
    transpose_pack_kernel<<<dim3(HD_ / 32, DM_ / 32), dim3(32, 8)>>>(Wk, pWkh, DM_, HD_);
    transpose_pack_kernel<<<dim3(HD_ / 32, DM_ / 32), dim3(32, 8)>>>(Wv, pWvh, DM_, HD_);
    transpose_pack_kernel<<<dim3(DM_ / 32, DM_ / 32), dim3(32, 8)>>>(Wo, pWoh, DM_, DM_);
    zero_kernel<<<(B_ * H_ * S_ + 255) / 256, 256>>>(pRS, B_ * H_ * S_);

    mma_qkvproj<<<dim3(18, M / 128), 256, SMEM64>>>(
        pxh, pWqh, pWkh, pWvh, bq, bk, bv, pQh, pKh, pVth);

    mma_scores<<<dim3(S_ / 128, S_ / 128, B_ * H_), 256, SMEM64>>>(
        pQh, pKh, scores, pRS);
    mma_softmax_pv<<<dim3(S_ / 128, B_ * H_), 256, SMEM32>>>(
        scores, pRS, pVth, pAh);

    mma_out<<<dim3(DM_ / 128, M / 128), 256, SMEM64>>>(pAh, pWoh, bo, out);
}

// round 14
// speedup vs baseline: 1.0005x; 1.0005x over previous
#include <cuda_runtime.h>
#include <cuda_fp16.h>
#include <cstdint>

// Problem dims
#define B_  4
#define S_  2048
#define DM_ 2048
#define H_  16
#define HD_ 128
#define SCALE_ 0.08838834764831843f   // 1/sqrt(128)

typedef __half h16;

// ---------------- scratch (__device__ globals) ----------------
__device__ h16 g_xh[(size_t)B_ * S_ * DM_];       // single fp16
__device__ h16 g_Qh[(size_t)B_ * S_ * DM_];
__device__ h16 g_Kh[(size_t)B_ * S_ * HD_];
__device__ h16 g_Vth[(size_t)B_ * HD_ * S_];      // [B][128][2048]
__device__ h16 g_attnh[(size_t)B_ * S_ * DM_];
__device__ h16 g_Wqh[(size_t)DM_ * DM_];          // transposed [N][K]
__device__ h16 g_Wkh[(size_t)HD_ * DM_];
__device__ h16 g_Wvh[(size_t)HD_ * DM_];
__device__ h16 g_Woh[(size_t)DM_ * DM_];
__device__ float g_rowsum[(size_t)B_ * H_ * S_];

// ---------------- smem layouts ----------------
// BK=64 cores: 3-stage ring; stage = {A, B}, each 128 x 72 fp16 = 18432 B
#define LDT64   72
#define TILE64  (128 * LDT64 * 2)         // 18432
#define STAGE64 (2 * TILE64)              // 36864
#define AUX64   (3 * STAGE64)             // 110592 (staging 67584 unions below)
#define RED64   (AUX64 + 512)
#define SMEM64  (AUX64 + 1536)            // 112128
// BK=32 PV core: 3-stage ring; stage = {A, B}, each 128 x 40 fp16 = 10240 B
#define LDT32   40
#define TILE32  10240
#define STAGE32 (2 * TILE32)              // 20480; x3 = 61440
#define AUX32   67584                     // after fp32 staging 128x132x4
#define SMEM32  69632

// ---------------- low-level helpers ----------------
__device__ __forceinline__ uint32_t smem_u32(const void* p) {
    uint32_t a;
    asm("{ .reg .u64 t; cvta.to.shared.u64 t, %1; cvt.u32.u64 %0, t; }" : "=r"(a) : "l"(p));
    return a;
}
__device__ __forceinline__ void cp16(uint32_t s, const void* g) {
    asm volatile("cp.async.ca.shared.global [%0], [%1], 16;"
                 :: "r"(s), "l"(__cvta_generic_to_global(g)));
}
#define CP_COMMIT() asm volatile("cp.async.commit_group;" ::: "memory")
#define CP_WAIT1()  asm volatile("cp.async.wait_group 1;" ::: "memory")
__device__ __forceinline__ void ldsm4(uint32_t* r, uint32_t a) {
    asm volatile("ldmatrix.sync.aligned.m8n8.x4.shared.b16 {%0,%1,%2,%3}, [%4];"
        : "=r"(r[0]), "=r"(r[1]), "=r"(r[2]), "=r"(r[3]) : "r"(a));
}
__device__ __forceinline__ void mma_fp16(float* d, const uint32_t* a, uint32_t b0, uint32_t b1) {
    asm volatile("mma.sync.aligned.m16n8k16.row.col.f32.f16.f16.f32 "
        "{%0,%1,%2,%3}, {%4,%5,%6,%7}, {%8,%9}, {%0,%1,%2,%3};"
        : "+f"(d[0]), "+f"(d[1]), "+f"(d[2]), "+f"(d[3])
        : "r"(a[0]), "r"(a[1]), "r"(a[2]), "r"(a[3]), "r"(b0), "r"(b1));
}
__device__ __forceinline__ uint32_t hbits2(__half2 h) {
    return *reinterpret_cast<uint32_t*>(&h);
}
__device__ __forceinline__ void pack4h(float4 v, uint32_t& h0, uint32_t& h1) {
    __half2 a = __floats2half2_rn(v.x, v.y);
    __half2 b = __floats2half2_rn(v.z, v.w);
    h0 = hbits2(a); h1 = hbits2(b);
}

// ---------------- BK=64 tile movement ----------------
__device__ __forceinline__ void issue_tiles64(char* buf,
    const h16* __restrict__ Ag, size_t lda,
    const h16* __restrict__ Bg, size_t ldb,
    int k0, int tid)
{
    uint32_t sA = smem_u32(buf);
#pragma unroll
    for (int i = 0; i < 4; i++) {
        int idx = i * 256 + tid;              // 0..1023
        int r = idx >> 3, c8 = (idx & 7) * 8;
        cp16(sA + r * (LDT64 * 2) + c8 * 2, Ag + (size_t)r * lda + k0 + c8);
    }
    uint32_t sB = sA + TILE64;
#pragma unroll
    for (int i = 0; i < 4; i++) {
        int idx = i * 256 + tid;
        int r = idx >> 3, c8 = (idx & 7) * 8;
        cp16(sB + r * (LDT64 * 2) + c8 * 2, Bg + (size_t)r * ldb + k0 + c8);
    }
}
// BK=32 B-only (PV)
__device__ __forceinline__ void issue_B32(char* buf,
    const h16* __restrict__ Bg, size_t ldb, int k0, int tid)
{
    uint32_t sB = smem_u32(buf) + TILE32;
#pragma unroll
    for (int i = 0; i < 2; i++) {
        int idx = i * 256 + tid;
        int r = idx >> 2, c8 = (idx & 3) * 8;
        cp16(sB + r * (LDT32 * 2) + c8 * 2, Bg + (size_t)r * ldb + k0 + c8);
    }
}

// ---------------- MMA compute: one chunk, warp 32x64, 1-term ----------------
template<int LDT, int TILE, int BK>
__device__ __forceinline__ void compute_chunk(float (*acc)[8][4], char* buf,
                                              int wm, int wn, int lane)
{
    h16* Ah = (h16*)buf;
    h16* Bh = (h16*)(buf + TILE);
    const int ar = lane & 15;
    const int acs = (lane >> 4) << 3;
#pragma unroll
    for (int kk = 0; kk < BK; kk += 16) {
        const int ac = kk + acs;
        uint32_t aH[2][4];
#pragma unroll
        for (int mt = 0; mt < 2; mt++)
            ldsm4(aH[mt], smem_u32(Ah + (wm * 32 + mt * 16 + ar) * LDT + ac));
#pragma unroll
        for (int p = 0; p < 4; p++) {
            uint32_t bh[4];
            ldsm4(bh, smem_u32(Bh + (wn * 64 + p * 16 + ar) * LDT + ac));
#pragma unroll
            for (int mt = 0; mt < 2; mt++) {
                mma_fp16(acc[mt][2 * p],     aH[mt], bh[0], bh[2]);
                mma_fp16(acc[mt][2 * p + 1], aH[mt], bh[1], bh[3]);
            }
        }
    }
}

// BK=64 pipelined core: 3-stage ring, ONE sync per chunk
__device__ __forceinline__ void gemm_core_h(float (*acc)[8][4],
    const h16* __restrict__ Ag, size_t lda,
    const h16* __restrict__ Bg, size_t ldb,
    int Kdim, char* smem)
{
    const int tid = threadIdx.x, wid = tid >> 5, lane = tid & 31;
    const int wm = wid & 3, wn = wid >> 2;
    const int nC = Kdim >> 6;
    issue_tiles64(smem, Ag, lda, Bg, ldb, 0, tid); CP_COMMIT();
    if (nC > 1) issue_tiles64(smem + STAGE64, Ag, lda, Bg, ldb, 64, tid);
    CP_COMMIT();
#pragma unroll 1
    for (int c = 0; c < nC; c++) {
        CP_WAIT1();
        __syncthreads();                       // chunk c ready; buf (c+2)%3 freed
        if (c + 2 < nC)
            issue_tiles64(smem + ((c + 2) % 3) * STAGE64, Ag, lda, Bg, ldb,
                          (c + 2) * 64, tid);
        CP_COMMIT();
        compute_chunk<LDT64, TILE64, 64>(acc, smem + (c % 3) * STAGE64, wm, wn, lane);
    }
    asm volatile("cp.async.wait_all;" ::: "memory");
    __syncthreads();
}

// PV core: BK=32, 3-stage ring, one sync. A = fp32 scores with register
// double-buffer prefetch: normalize by rinv, write back, pack fp16 to smem.
__device__ __forceinline__ void gemm_core_pv(float (*acc)[8][4],
    float* __restrict__ A, size_t lda,
    const h16* __restrict__ Bg, size_t ldb,
    int Kdim, char* smem, const float* __restrict__ rinv)
{
    const int tid = threadIdx.x, wid = tid >> 5, lane = tid & 31;
    const int wm = wid & 3, wn = wid >> 2;
    const int nC = Kdim >> 5;                     // 64
    issue_B32(smem, Bg, ldb, 0, tid); CP_COMMIT();
    issue_B32(smem + STAGE32, Bg, ldb, 32, tid); CP_COMMIT();

    float4 pr[4];
#pragma unroll
    for (int i = 0; i < 4; i++) {
        int idx = i * 256 + tid;
        int rr = idx >> 3, cc = (idx & 7) * 4;
        pr[i] = *(const float4*)(A + (size_t)rr * lda + cc);
    }
#pragma unroll 1
    for (int c = 0; c < nC; c++) {
        char* buf = smem + (c % 3) * STAGE32;
        CP_WAIT1();
        // fill A chunk c into buf c%3 (freed 2 iterations ago)
        h16* Ah = (h16*)buf;
#pragma unroll
        for (int i = 0; i < 4; i++) {
            int idx = i * 256 + tid;
            int rr = idx >> 3, cc = (idx & 7) * 4;
            float ri = rinv[rr];
            float4 v = pr[i];
            v.x *= ri; v.y *= ri; v.z *= ri; v.w *= ri;
            *(float4*)(A + (size_t)rr * lda + c * 32 + cc) = v;
            uint32_t h0, h1; pack4h(v, h0, h1);
            *(uint2*)(Ah + rr * LDT32 + cc) = make_uint2(h0, h1);
        }
        if (c + 1 < nC) {
#pragma unroll
            for (int i = 0; i < 4; i++) {
                int idx = i * 256 + tid;
                int rr = idx >> 3, cc = (idx & 7) * 4;
                pr[i] = *(const float4*)(A + (size_t)rr * lda + (c + 1) * 32 + cc);
            }
        }
        __syncthreads();                       // A(c) visible; B(c) ready; buf (c+2)%3 freed
        if (c + 2 < nC)
            issue_B32(smem + ((c + 2) % 3) * STAGE32, Bg, ldb, (c + 2) * 32, tid);
        CP_COMMIT();
        compute_chunk<LDT32, TILE32, 32>(acc, buf, wm, wn, lane);
    }
    asm volatile("cp.async.wait_all;" ::: "memory");
    __syncthreads();
}

// stage acc (fp32) into smem [128][132]
__device__ __forceinline__ void stage_acc(float (*acc)[8][4], float* stg, int wid, int lane) {
    int wm = wid & 3, wn = wid >> 2;
    int r0 = wm * 32 + (lane >> 2), c0 = wn * 64 + (lane & 3) * 2;
#pragma unroll
    for (int mt = 0; mt < 2; mt++)
#pragma unroll
        for (int nt = 0; nt < 8; nt++) {
            int r = r0 + mt * 16, c = c0 + nt * 8;
            *(float2*)&stg[r * 132 + c] = make_float2(acc[mt][nt][0], acc[mt][nt][1]);
            *(float2*)&stg[(r + 8) * 132 + c] = make_float2(acc[mt][nt][2], acc[mt][nt][3]);
        }
}

#define ZERO_ACC(acc) \
    _Pragma("unroll") for (int i_ = 0; i_ < 2; i_++) \
    _Pragma("unroll") for (int j_ = 0; j_ < 8; j_++) \
    _Pragma("unroll") for (int q_ = 0; q_ < 4; q_++) acc[i_][j_][q_] = 0.0f;

// ---------------- prep kernels ----------------
__global__ void split_x_kernel(const float* __restrict__ x, h16* __restrict__ xh, int n4) {
    int i = blockIdx.x * blockDim.x + threadIdx.x;
    if (i >= n4) return;
    float4 v = *(const float4*)(x + 4 * (size_t)i);
    uint32_t h0, h1; pack4h(v, h0, h1);
    *(uint2*)(xh + 4 * (size_t)i) = make_uint2(h0, h1);
}
__global__ void transpose_pack_kernel(const float* __restrict__ src,
                                      h16* __restrict__ dh, int M, int N) {
    __shared__ float t[32][33];
    int bx = blockIdx.x * 32, by = blockIdx.y * 32;
    int x = threadIdx.x, y0 = threadIdx.y;
#pragma unroll
    for (int j = 0; j < 32; j += 8)
        t[y0 + j][x] = src[(size_t)(by + y0 + j) * N + bx + x];
    __syncthreads();
#pragma unroll
    for (int j = 0; j < 32; j += 8)
        dh[(size_t)(bx + y0 + j) * M + by + x] = __float2half_rn(t[x][y0 + j]);
}
__global__ void zero_kernel(float* p, int n) {
    int i = blockIdx.x * blockDim.x + threadIdx.x;
    if (i < n) p[i] = 0.0f;
}

// ---------------- fused Q + K + V projection ----------------
// grid (18, 64): x<16 -> Q col tile x; x==16 -> K; x==17 -> V
__global__ __launch_bounds__(256, 2) void mma_qkvproj(
    const h16* __restrict__ Ag,
    const h16* __restrict__ Wqh, const h16* __restrict__ Wkh, const h16* __restrict__ Wvh,
    const float* __restrict__ bq, const float* __restrict__ bk, const float* __restrict__ bv,
    h16* __restrict__ Qh, h16* __restrict__ Kh, h16* __restrict__ Vth)
{
    extern __shared__ __align__(16) char smem[];
    const int tid = threadIdx.x, wid = tid >> 5, lane = tid & 31;
    const int bx = blockIdx.x;
    const int row0 = blockIdx.y * 128;

    const h16* Bg;
    const float* bias;
    if (bx < 16)      { Bg = Wqh + (size_t)bx * 128 * DM_; bias = bq + bx * 128; }
    else if (bx == 16){ Bg = Wkh; bias = bk; }
    else              { Bg = Wvh; bias = bv; }

    float* bs = (float*)(smem + AUX64);
    if (tid < 128) bs[tid] = bias[tid];

    float acc[2][8][4];
    ZERO_ACC(acc)
    gemm_core_h(acc, Ag + (size_t)row0 * DM_, DM_, Bg, DM_, DM_, smem);

    float* stg = (float*)smem;
    stage_acc(acc, stg, wid, lane);
    __syncthreads();
    if (bx < 16) {
        // Q: single fp16 [B*S, DM], col block bx*128
#pragma unroll 1
        for (int i = 0; i < 16; i++) {
            int idx = i * 256 + tid;
            int rr = idx >> 5, c4 = (idx & 31) << 2;
            float4 v = *(float4*)&stg[rr * 132 + c4];
            v.x += bs[c4]; v.y += bs[c4 + 1]; v.z += bs[c4 + 2]; v.w += bs[c4 + 3];
            uint32_t h0, h1; pack4h(v, h0, h1);
            *(uint2*)(Qh + (size_t)(row0 + rr) * DM_ + bx * 128 + c4) = make_uint2(h0, h1);
        }
    } else if (bx == 16) {
        // K: single fp16, row-major [B*S, HD]
#pragma unroll 1
        for (int i = 0; i < 16; i++) {
            int idx = i * 256 + tid;
            int rr = idx >> 5, c4 = (idx & 31) << 2;
            float4 v = *(float4*)&stg[rr * 132 + c4];
            v.x += bs[c4]; v.y += bs[c4 + 1]; v.z += bs[c4 + 2]; v.w += bs[c4 + 3];
            uint32_t h0, h1; pack4h(v, h0, h1);
            *(uint2*)(Kh + (size_t)(row0 + rr) * HD_ + c4) = make_uint2(h0, h1);
        }
    } else {
        // V: single fp16, transposed [B][HD][S]
        int b = row0 >> 11;
        int s0 = row0 & (S_ - 1);
        h16* Vb = Vth + (size_t)b * HD_ * S_;
#pragma unroll 1
        for (int i = 0; i < 64; i++) {
            int idx = i * 256 + tid;
            int m = idx & 127, n = idx >> 7;
            Vb[(size_t)n * S_ + s0 + m] = __float2half_rn(stg[m * 132 + n] + bs[n]);
        }
    }
}

// ---------------- scores: E = exp(scale * Q Kt) fp32 out + rowsums ----------------
__global__ __launch_bounds__(256, 2) void mma_scores(
    const h16* __restrict__ Qh,
    const h16* __restrict__ Kh,
    float* __restrict__ scores, float* __restrict__ rowsum)
{
    extern __shared__ __align__(16) char smem[];
    const int tid = threadIdx.x, wid = tid >> 5, lane = tid & 31;
    const int bh = blockIdx.z;
    const int b = bh >> 4, hd = bh & 15;
    const int row0 = blockIdx.y * 128, col0 = blockIdx.x * 128;

    float acc[2][8][4];
    ZERO_ACC(acc)
    gemm_core_h(acc,
        Qh + ((size_t)b * S_ + row0) * DM_ + hd * HD_, DM_,
        Kh + ((size_t)b * S_ + col0) * HD_, HD_, HD_, smem);

    float* stg = (float*)smem;
    float* red = (float*)(smem + RED64);
    const int wm = wid & 3, wn = wid >> 2;
    const int r0 = wm * 32 + (lane >> 2), c0 = wn * 64 + (lane & 3) * 2;
    float sums[2][2] = {{0.f, 0.f}, {0.f, 0.f}};
#pragma unroll
    for (int mt = 0; mt < 2; mt++)
#pragma unroll
        for (int nt = 0; nt < 8; nt++) {
            float e0 = __expf(acc[mt][nt][0] * SCALE_);
            float e1 = __expf(acc[mt][nt][1] * SCALE_);
            float e2 = __expf(acc[mt][nt][2] * SCALE_);
            float e3 = __expf(acc[mt][nt][3] * SCALE_);
            int r = r0 + mt * 16, c = c0 + nt * 8;
            *(float2*)&stg[r * 132 + c] = make_float2(e0, e1);
            *(float2*)&stg[(r + 8) * 132 + c] = make_float2(e2, e3);
            sums[mt][0] += e0 + e1;
            sums[mt][1] += e2 + e3;
        }
#pragma unroll
    for (int mt = 0; mt < 2; mt++)
#pragma unroll
        for (int hh = 0; hh < 2; hh++) {
            float v = sums[mt][hh];
            v += __shfl_xor_sync(0xFFFFFFFFu, v, 1);
            v += __shfl_xor_sync(0xFFFFFFFFu, v, 2);
            sums[mt][hh] = v;
        }
    if ((lane & 3) == 0) {
#pragma unroll
        for (int mt = 0; mt < 2; mt++)
#pragma unroll
            for (int hh = 0; hh < 2; hh++)
                red[(wm * 32 + mt * 16 + hh * 8 + (lane >> 2)) * 2 + wn] = sums[mt][hh];
    }
    __syncthreads();
    if (tid < 128)
        atomicAdd(&rowsum[(size_t)bh * S_ + row0 + tid], red[tid * 2] + red[tid * 2 + 1]);

    float* Crow = scores + ((size_t)bh * S_ + row0) * S_ + col0;
#pragma unroll 1
    for (int i = 0; i < 16; i++) {
        int idx = i * 256 + tid;
        int rr = idx >> 5, c4 = (idx & 31) << 2;
        *(float4*)&Crow[(size_t)rr * S_ + c4] = *(float4*)&stg[rr * 132 + c4];
    }
}

// ---------------- normalize scores in place + PV (single-fp16 epilogue) ----------------
__global__ __launch_bounds__(256, 2) void mma_softmax_pv(
    float* __restrict__ scores, const float* __restrict__ rowsum,
    const h16* __restrict__ Vth, h16* __restrict__ attnh)
{
    extern __shared__ __align__(16) char smem[];
    const int tid = threadIdx.x, wid = tid >> 5, lane = tid & 31;
    const int bh = blockIdx.y;
    const int b = bh >> 4, hd = bh & 15;
    const int row0 = blockIdx.x * 128;

    float* rinv = (float*)(smem + AUX32);
    if (tid < 128) rinv[tid] = 1.0f / rowsum[(size_t)bh * S_ + row0 + tid];
    __syncthreads();

    float acc[2][8][4];
    ZERO_ACC(acc)
    gemm_core_pv(acc, scores + ((size_t)bh * S_ + row0) * S_, S_,
                 Vth + (size_t)b * HD_ * S_, S_, S_, smem, rinv);

    float* stg = (float*)smem;
    stage_acc(acc, stg, wid, lane);
    __syncthreads();
    h16* Cb = attnh + ((size_t)b * S_ + row0) * DM_ + hd * HD_;
#pragma unroll 1
    for (int i = 0; i < 16; i++) {
        int idx = i * 256 + tid;
        int rr = idx >> 5, c4 = (idx & 31) << 2;
        float4 v = *(float4*)&stg[rr * 132 + c4];
        uint32_t h0, h1; pack4h(v, h0, h1);
        *(uint2*)(Cb + (size_t)rr * DM_ + c4) = make_uint2(h0, h1);
    }
}

// ---------------- output GEMM (fp32 + bias epilogue) ----------------
__global__ __launch_bounds__(256, 2) void mma_out(
    const h16* __restrict__ Ag,
    const h16* __restrict__ Bg,
    const float* __restrict__ bias, float* __restrict__ C)
{
    extern __shared__ __align__(16) char smem[];
    const int tid = threadIdx.x, wid = tid >> 5, lane = tid & 31;
    const int row0 = blockIdx.y * 128, col0 = blockIdx.x * 128;

    float* bs = (float*)(smem + AUX64);
    if (tid < 128) bs[tid] = bias[col0 + tid];

    float acc[2][8][4];
    ZERO_ACC(acc)
    gemm_core_h(acc, Ag + (size_t)row0 * DM_, DM_,
                Bg + (size_t)col0 * DM_, DM_, DM_, smem);

    float* stg = (float*)smem;
    stage_acc(acc, stg, wid, lane);
    __syncthreads();
#pragma unroll 1
    for (int i = 0; i < 16; i++) {
        int idx = i * 256 + tid;
        int rr = idx >> 5, c4 = (idx & 31) << 2;
        float4 v = *(float4*)&stg[rr * 132 + c4];
        v.x += bs[c4]; v.y += bs[c4 + 1]; v.z += bs[c4 + 2]; v.w += bs[c4 + 3];
        *(float4*)&C[(size_t)(row0 + rr) * DM_ + col0 + c4] = v;
    }
}

// ---------------- launch ----------------
extern "C" void kernel_launch(void* const* d_in, const int* in_sizes, int n_in,
                              void* d_out, int out_size)
{
    const float* x  = (const float*)d_in[0];
    const float* Wq = (const float*)d_in[1];
    const float* bq = (const float*)d_in[2];
    const float* Wk = (const float*)d_in[3];
    const float* bk = (const float*)d_in[4];
    const float* Wv = (const float*)d_in[5];
    const float* bv = (const float*)d_in[6];
    const float* Wo = (const float*)d_in[7];
    const float* bo = (const float*)d_in[8];

    float* out = (float*)d_out;
    float* scores = out + (size_t)B_ * S_ * DM_;

    h16 *pxh, *pQh, *pKh, *pVth, *pAh;
    h16 *pWqh, *pWkh, *pWvh, *pWoh;
    float* pRS;
    cudaGetSymbolAddress((void**)&pxh, g_xh);
    cudaGetSymbolAddress((void**)&pQh, g_Qh);
    cudaGetSymbolAddress((void**)&pKh, g_Kh);
    cudaGetSymbolAddress((void**)&pVth, g_Vth);
    cudaGetSymbolAddress((void**)&pAh, g_attnh);
    cudaGetSymbolAddress((void**)&pWqh, g_Wqh);
    cudaGetSymbolAddress((void**)&pWkh, g_Wkh);
    cudaGetSymbolAddress((void**)&pWvh, g_Wvh);
    cudaGetSymbolAddress((void**)&pWoh, g_Woh);
    cudaGetSymbolAddress((void**)&pRS, g_rowsum);

    static int smem_set = 0;
    if (!smem_set) {
        cudaFuncSetAttribute(mma_qkvproj, cudaFuncAttributeMaxDynamicSharedMemorySize, SMEM64);
        cudaFuncSetAttribute(mma_scores, cudaFuncAttributeMaxDynamicSharedMemorySize, SMEM64);
        cudaFuncSetAttribute(mma_softmax_pv, cudaFuncAttributeMaxDynamicSharedMemorySize, SMEM32);
        cudaFuncSetAttribute(mma_out, cudaFuncAttributeMaxDynamicSharedMemorySize, SMEM64);
        smem_set = 1;
    }

    const int M = B_ * S_;   // 8192
    split_x_kernel<<<(M * DM_ / 4 + 255) / 256, 256>>>(x, pxh, M * DM_ / 4);
    transpose_pack_kernel<<<dim3(DM_ / 32, DM_ / 32), dim3(32, 8)>>>(Wq, pWqh, DM_, DM_);
    transpose_pack_kernel<<<dim3(HD_ / 32, DM_ / 32), dim3(32, 8)>>>(Wk, pWkh, DM_, HD_);
    transpose_pack_kernel<<<dim3(HD_ / 32, DM_ / 32), dim3(32, 8)>>>(Wv, pWvh, DM_, HD_);
    transpose_pack_kernel<<<dim3(DM_ / 32, DM_ / 32), dim3(32, 8)>>>(Wo, pWoh, DM_, DM_);
    zero_kernel<<<(B_ * H_ * S_ + 255) / 256, 256>>>(pRS, B_ * H_ * S_);

    mma_qkvproj<<<dim3(18, M / 128), 256, SMEM64>>>(
        pxh, pWqh, pWkh, pWvh, bq, bk, bv, pQh, pKh, pVth);

    mma_scores<<<dim3(S_ / 128, S_ / 128, B_ * H_), 256, SMEM64>>>(
        pQh, pKh, scores, pRS);
    mma_softmax_pv<<<dim3(S_ / 128, B_ * H_), 256, SMEM32>>>(
        scores, pRS, pVth, pAh);

    mma_out<<<dim3(DM_ / 128, M / 128), 256, SMEM64>>>(pAh, pWoh, bo, out);
}

// round 15
// speedup vs baseline: 1.0014x; 1.0010x over previous
#include <cuda_runtime.h>
#include <cuda_fp16.h>
#include <cstdint>

// Problem dims
#define B_  4
#define S_  2048
#define DM_ 2048
#define H_  16
#define HD_ 128
#define SCALE_ 0.08838834764831843f   // 1/sqrt(128)

typedef __half h16;

// ---------------- scratch (__device__ globals) ----------------
__device__ h16 g_xh[(size_t)B_ * S_ * DM_];       // single fp16
__device__ h16 g_Qh[(size_t)B_ * S_ * DM_];
__device__ h16 g_Kh[(size_t)B_ * S_ * HD_];
__device__ h16 g_Vth[(size_t)B_ * HD_ * S_];      // [B][128][2048]
__device__ h16 g_attnh[(size_t)B_ * S_ * DM_];
__device__ h16 g_Wqh[(size_t)DM_ * DM_];          // transposed [N][K]
__device__ h16 g_Wkh[(size_t)HD_ * DM_];
__device__ h16 g_Wvh[(size_t)HD_ * DM_];
__device__ h16 g_Woh[(size_t)DM_ * DM_];
__device__ float g_rowsum[(size_t)B_ * H_ * S_];

// ---------------- smem layouts ----------------
// BK=64 cores: 3-stage ring; stage = {A, B}, each 128 x 72 fp16 = 18432 B
#define LDT64   72
#define TILE64  (128 * LDT64 * 2)         // 18432
#define STAGE64 (2 * TILE64)              // 36864
#define AUX64   (3 * STAGE64)             // 110592 (staging 67584 unions below)
#define RED64   (AUX64 + 512)
#define SMEM64  (AUX64 + 1536)            // 112128
// BK=32 PV core: 3-stage ring; stage = {A, B}, each 128 x 40 fp16 = 10240 B
#define LDT32   40
#define TILE32  10240
#define STAGE32 (2 * TILE32)              // 20480; x3 = 61440
#define AUX32   67584                     // after fp32 staging 128x132x4
#define SMEM32  69632

// ---------------- low-level helpers ----------------
__device__ __forceinline__ uint32_t smem_u32(const void* p) {
    uint32_t a;
    asm("{ .reg .u64 t; cvta.to.shared.u64 t, %1; cvt.u32.u64 %0, t; }" : "=r"(a) : "l"(p));
    return a;
}
__device__ __forceinline__ void cp16(uint32_t s, const void* g) {
    asm volatile("cp.async.ca.shared.global [%0], [%1], 16;"
                 :: "r"(s), "l"(__cvta_generic_to_global(g)));
}
#define CP_COMMIT() asm volatile("cp.async.commit_group;" ::: "memory")
#define CP_WAIT1()  asm volatile("cp.async.wait_group 1;" ::: "memory")
__device__ __forceinline__ void ldsm4(uint32_t* r, uint32_t a) {
    asm volatile("ldmatrix.sync.aligned.m8n8.x4.shared.b16 {%0,%1,%2,%3}, [%4];"
        : "=r"(r[0]), "=r"(r[1]), "=r"(r[2]), "=r"(r[3]) : "r"(a));
}
__device__ __forceinline__ void mma_fp16(float* d, const uint32_t* a, uint32_t b0, uint32_t b1) {
    asm volatile("mma.sync.aligned.m16n8k16.row.col.f32.f16.f16.f32 "
        "{%0,%1,%2,%3}, {%4,%5,%6,%7}, {%8,%9}, {%0,%1,%2,%3};"
        : "+f"(d[0]), "+f"(d[1]), "+f"(d[2]), "+f"(d[3])
        : "r"(a[0]), "r"(a[1]), "r"(a[2]), "r"(a[3]), "r"(b0), "r"(b1));
}
__device__ __forceinline__ uint32_t hbits2(__half2 h) {
    return *reinterpret_cast<uint32_t*>(&h);
}
__device__ __forceinline__ void pack4h(float4 v, uint32_t& h0, uint32_t& h1) {
    __half2 a = __floats2half2_rn(v.x, v.y);
    __half2 b = __floats2half2_rn(v.z, v.w);
    h0 = hbits2(a); h1 = hbits2(b);
}

// ---------------- BK=64 tile movement ----------------
__device__ __forceinline__ void issue_tiles64(char* buf,
    const h16* __restrict__ Ag, size_t lda,
    const h16* __restrict__ Bg, size_t ldb,
    int k0, int tid)
{
    uint32_t sA = smem_u32(buf);
#pragma unroll
    for (int i = 0; i < 4; i++) {
        int idx = i * 256 + tid;              // 0..1023
        int r = idx >> 3, c8 = (idx & 7) * 8;
        cp16(sA + r * (LDT64 * 2) + c8 * 2, Ag + (size_t)r * lda + k0 + c8);
    }
    uint32_t sB = sA + TILE64;
#pragma unroll
    for (int i = 0; i < 4; i++) {
        int idx = i * 256 + tid;
        int r = idx >> 3, c8 = (idx & 7) * 8;
        cp16(sB + r * (LDT64 * 2) + c8 * 2, Bg + (size_t)r * ldb + k0 + c8);
    }
}
// BK=32 B-only (PV)
__device__ __forceinline__ void issue_B32(char* buf,
    const h16* __restrict__ Bg, size_t ldb, int k0, int tid)
{
    uint32_t sB = smem_u32(buf) + TILE32;
#pragma unroll
    for (int i = 0; i < 2; i++) {
        int idx = i * 256 + tid;
        int r = idx >> 2, c8 = (idx & 3) * 8;
        cp16(sB + r * (LDT32 * 2) + c8 * 2, Bg + (size_t)r * ldb + k0 + c8);
    }
}

// ---------------- MMA compute: one chunk, warp 32x64, 1-term ----------------
template<int LDT, int TILE, int BK>
__device__ __forceinline__ void compute_chunk(float (*acc)[8][4], char* buf,
                                              int wm, int wn, int lane)
{
    h16* Ah = (h16*)buf;
    h16* Bh = (h16*)(buf + TILE);
    const int ar = lane & 15;
    const int acs = (lane >> 4) << 3;
#pragma unroll
    for (int kk = 0; kk < BK; kk += 16) {
        const int ac = kk + acs;
        uint32_t aH[2][4];
#pragma unroll
        for (int mt = 0; mt < 2; mt++)
            ldsm4(aH[mt], smem_u32(Ah + (wm * 32 + mt * 16 + ar) * LDT + ac));
#pragma unroll
        for (int p = 0; p < 4; p++) {
            uint32_t bh[4];
            ldsm4(bh, smem_u32(Bh + (wn * 64 + p * 16 + ar) * LDT + ac));
#pragma unroll
            for (int mt = 0; mt < 2; mt++) {
                mma_fp16(acc[mt][2 * p],     aH[mt], bh[0], bh[2]);
                mma_fp16(acc[mt][2 * p + 1], aH[mt], bh[1], bh[3]);
            }
        }
    }
}

// BK=64 pipelined core: 3-stage ring, ONE sync per chunk
__device__ __forceinline__ void gemm_core_h(float (*acc)[8][4],
    const h16* __restrict__ Ag, size_t lda,
    const h16* __restrict__ Bg, size_t ldb,
    int Kdim, char* smem)
{
    const int tid = threadIdx.x, wid = tid >> 5, lane = tid & 31;
    const int wm = wid & 3, wn = wid >> 2;
    const int nC = Kdim >> 6;
    issue_tiles64(smem, Ag, lda, Bg, ldb, 0, tid); CP_COMMIT();
    if (nC > 1) issue_tiles64(smem + STAGE64, Ag, lda, Bg, ldb, 64, tid);
    CP_COMMIT();
#pragma unroll 1
    for (int c = 0; c < nC; c++) {
        CP_WAIT1();
        __syncthreads();                       // chunk c ready; buf (c+2)%3 freed
        if (c + 2 < nC)
            issue_tiles64(smem + ((c + 2) % 3) * STAGE64, Ag, lda, Bg, ldb,
                          (c + 2) * 64, tid);
        CP_COMMIT();
        compute_chunk<LDT64, TILE64, 64>(acc, smem + (c % 3) * STAGE64, wm, wn, lane);
    }
    asm volatile("cp.async.wait_all;" ::: "memory");
    __syncthreads();
}

// PV core: BK=32, 3-stage ring, one sync. A = fp32 scores with register
// double-buffer prefetch: normalize by rinv, write back, pack fp16 to smem.
__device__ __forceinline__ void gemm_core_pv(float (*acc)[8][4],
    float* __restrict__ A, size_t lda,
    const h16* __restrict__ Bg, size_t ldb,
    int Kdim, char* smem, const float* __restrict__ rinv)
{
    const int tid = threadIdx.x, wid = tid >> 5, lane = tid & 31;
    const int wm = wid & 3, wn = wid >> 2;
    const int nC = Kdim >> 5;                     // 64
    issue_B32(smem, Bg, ldb, 0, tid); CP_COMMIT();
    issue_B32(smem + STAGE32, Bg, ldb, 32, tid); CP_COMMIT();

    float4 pr[4];
#pragma unroll
    for (int i = 0; i < 4; i++) {
        int idx = i * 256 + tid;
        int rr = idx >> 3, cc = (idx & 7) * 4;
        pr[i] = *(const float4*)(A + (size_t)rr * lda + cc);
    }
#pragma unroll 1
    for (int c = 0; c < nC; c++) {
        char* buf = smem + (c % 3) * STAGE32;
        CP_WAIT1();
        // fill A chunk c into buf c%3 (freed 2 iterations ago)
        h16* Ah = (h16*)buf;
#pragma unroll
        for (int i = 0; i < 4; i++) {
            int idx = i * 256 + tid;
            int rr = idx >> 3, cc = (idx & 7) * 4;
            float ri = rinv[rr];
            float4 v = pr[i];
            v.x *= ri; v.y *= ri; v.z *= ri; v.w *= ri;
            *(float4*)(A + (size_t)rr * lda + c * 32 + cc) = v;
            uint32_t h0, h1; pack4h(v, h0, h1);
            *(uint2*)(Ah + rr * LDT32 + cc) = make_uint2(h0, h1);
        }
        if (c + 1 < nC) {
#pragma unroll
            for (int i = 0; i < 4; i++) {
                int idx = i * 256 + tid;
                int rr = idx >> 3, cc = (idx & 7) * 4;
                pr[i] = *(const float4*)(A + (size_t)rr * lda + (c + 1) * 32 + cc);
            }
        }
        __syncthreads();                       // A(c) visible; B(c) ready; buf (c+2)%3 freed
        if (c + 2 < nC)
            issue_B32(smem + ((c + 2) % 3) * STAGE32, Bg, ldb, (c + 2) * 32, tid);
        CP_COMMIT();
        compute_chunk<LDT32, TILE32, 32>(acc, buf, wm, wn, lane);
    }
    asm volatile("cp.async.wait_all;" ::: "memory");
    __syncthreads();
}

// stage acc (fp32) into smem [128][132]
__device__ __forceinline__ void stage_acc(float (*acc)[8][4], float* stg, int wid, int lane) {
    int wm = wid & 3, wn = wid >> 2;
    int r0 = wm * 32 + (lane >> 2), c0 = wn * 64 + (lane & 3) * 2;
#pragma unroll
    for (int mt = 0; mt < 2; mt++)
#pragma unroll
        for (int nt = 0; nt < 8; nt++) {
            int r = r0 + mt * 16, c = c0 + nt * 8;
            *(float2*)&stg[r * 132 + c] = make_float2(acc[mt][nt][0], acc[mt][nt][1]);
            *(float2*)&stg[(r + 8) * 132 + c] = make_float2(acc[mt][nt][2], acc[mt][nt][3]);
        }
}

#define ZERO_ACC(acc) \
    _Pragma("unroll") for (int i_ = 0; i_ < 2; i_++) \
    _Pragma("unroll") for (int j_ = 0; j_ < 8; j_++) \
    _Pragma("unroll") for (int q_ = 0; q_ < 4; q_++) acc[i_][j_][q_] = 0.0f;

// ---------------- prep kernels ----------------
__global__ void split_x_kernel(const float* __restrict__ x, h16* __restrict__ xh, int n4) {
    int i = blockIdx.x * blockDim.x + threadIdx.x;
    if (i >= n4) return;
    float4 v = *(const float4*)(x + 4 * (size_t)i);
    uint32_t h0, h1; pack4h(v, h0, h1);
    *(uint2*)(xh + 4 * (size_t)i) = make_uint2(h0, h1);
}
__global__ void transpose_pack_kernel(const float* __restrict__ src,
                                      h16* __restrict__ dh, int M, int N) {
    __shared__ float t[32][33];
    int bx = blockIdx.x * 32, by = blockIdx.y * 32;
    int x = threadIdx.x, y0 = threadIdx.y;
#pragma unroll
    for (int j = 0; j < 32; j += 8)
        t[y0 + j][x] = src[(size_t)(by + y0 + j) * N + bx + x];
    __syncthreads();
#pragma unroll
    for (int j = 0; j < 32; j += 8)
        dh[(size_t)(bx + y0 + j) * M + by + x] = __float2half_rn(t[x][y0 + j]);
}
__global__ void zero_kernel(float* p, int n) {
    int i = blockIdx.x * blockDim.x + threadIdx.x;
    if (i < n) p[i] = 0.0f;
}

// ---------------- fused Q + K + V projection ----------------
// grid (18, 64): x<16 -> Q col tile x; x==16 -> K; x==17 -> V
__global__ __launch_bounds__(256, 2) void mma_qkvproj(
    const h16* __restrict__ Ag,
    const h16* __restrict__ Wqh, const h16* __restrict__ Wkh, const h16* __restrict__ Wvh,
    const float* __restrict__ bq, const float* __restrict__ bk, const float* __restrict__ bv,
    h16* __restrict__ Qh, h16* __restrict__ Kh, h16* __restrict__ Vth)
{
    extern __shared__ __align__(16) char smem[];
    const int tid = threadIdx.x, wid = tid >> 5, lane = tid & 31;
    const int bx = blockIdx.x;
    const int row0 = blockIdx.y * 128;

    const h16* Bg;
    const float* bias;
    if (bx < 16)      { Bg = Wqh + (size_t)bx * 128 * DM_; bias = bq + bx * 128; }
    else if (bx == 16){ Bg = Wkh; bias = bk; }
    else              { Bg = Wvh; bias = bv; }

    float* bs = (float*)(smem + AUX64);
    if (tid < 128) bs[tid] = bias[tid];

    float acc[2][8][4];
    ZERO_ACC(acc)
    gemm_core_h(acc, Ag + (size_t)row0 * DM_, DM_, Bg, DM_, DM_, smem);

    float* stg = (float*)smem;
    stage_acc(acc, stg, wid, lane);
    __syncthreads();
    if (bx < 16) {
        // Q: single fp16 [B*S, DM], col block bx*128
#pragma unroll 1
        for (int i = 0; i < 16; i++) {
            int idx = i * 256 + tid;
            int rr = idx >> 5, c4 = (idx & 31) << 2;
            float4 v = *(float4*)&stg[rr * 132 + c4];
            v.x += bs[c4]; v.y += bs[c4 + 1]; v.z += bs[c4 + 2]; v.w += bs[c4 + 3];
            uint32_t h0, h1; pack4h(v, h0, h1);
            *(uint2*)(Qh + (size_t)(row0 + rr) * DM_ + bx * 128 + c4) = make_uint2(h0, h1);
        }
    } else if (bx == 16) {
        // K: single fp16, row-major [B*S, HD]
#pragma unroll 1
        for (int i = 0; i < 16; i++) {
            int idx = i * 256 + tid;
            int rr = idx >> 5, c4 = (idx & 31) << 2;
            float4 v = *(float4*)&stg[rr * 132 + c4];
            v.x += bs[c4]; v.y += bs[c4 + 1]; v.z += bs[c4 + 2]; v.w += bs[c4 + 3];
            uint32_t h0, h1; pack4h(v, h0, h1);
            *(uint2*)(Kh + (size_t)(row0 + rr) * HD_ + c4) = make_uint2(h0, h1);
        }
    } else {
        // V: single fp16, transposed [B][HD][S]
        int b = row0 >> 11;
        int s0 = row0 & (S_ - 1);
        h16* Vb = Vth + (size_t)b * HD_ * S_;
#pragma unroll 1
        for (int i = 0; i < 64; i++) {
            int idx = i * 256 + tid;
            int m = idx & 127, n = idx >> 7;
            Vb[(size_t)n * S_ + s0 + m] = __float2half_rn(stg[m * 132 + n] + bs[n]);
        }
    }
}

// ---------------- scores: E = exp(scale * Q Kt) fp32 out + rowsums ----------------
__global__ __launch_bounds__(256, 2) void mma_scores(
    const h16* __restrict__ Qh,
    const h16* __restrict__ Kh,
    float* __restrict__ scores, float* __restrict__ rowsum)
{
    extern __shared__ __align__(16) char smem[];
    const int tid = threadIdx.x, wid = tid >> 5, lane = tid & 31;
    const int bh = blockIdx.z;
    const int b = bh >> 4, hd = bh & 15;
    const int row0 = blockIdx.y * 128, col0 = blockIdx.x * 128;

    float acc[2][8][4];
    ZERO_ACC(acc)
    gemm_core_h(acc,
        Qh + ((size_t)b * S_ + row0) * DM_ + hd * HD_, DM_,
        Kh + ((size_t)b * S_ + col0) * HD_, HD_, HD_, smem);

    float* stg = (float*)smem;
    float* red = (float*)(smem + RED64);
    const int wm = wid & 3, wn = wid >> 2;
    const int r0 = wm * 32 + (lane >> 2), c0 = wn * 64 + (lane & 3) * 2;
    float sums[2][2] = {{0.f, 0.f}, {0.f, 0.f}};
#pragma unroll
    for (int mt = 0; mt < 2; mt++)
#pragma unroll
        for (int nt = 0; nt < 8; nt++) {
            float e0 = __expf(acc[mt][nt][0] * SCALE_);
            float e1 = __expf(acc[mt][nt][1] * SCALE_);
            float e2 = __expf(acc[mt][nt][2] * SCALE_);
            float e3 = __expf(acc[mt][nt][3] * SCALE_);
            int r = r0 + mt * 16, c = c0 + nt * 8;
            *(float2*)&stg[r * 132 + c] = make_float2(e0, e1);
            *(float2*)&stg[(r + 8) * 132 + c] = make_float2(e2, e3);
            sums[mt][0] += e0 + e1;
            sums[mt][1] += e2 + e3;
        }
#pragma unroll
    for (int mt = 0; mt < 2; mt++)
#pragma unroll
        for (int hh = 0; hh < 2; hh++) {
            float v = sums[mt][hh];
            v += __shfl_xor_sync(0xFFFFFFFFu, v, 1);
            v += __shfl_xor_sync(0xFFFFFFFFu, v, 2);
            sums[mt][hh] = v;
        }
    if ((lane & 3) == 0) {
#pragma unroll
        for (int mt = 0; mt < 2; mt++)
#pragma unroll
            for (int hh = 0; hh < 2; hh++)
                red[(wm * 32 + mt * 16 + hh * 8 + (lane >> 2)) * 2 + wn] = sums[mt][hh];
    }
    __syncthreads();
    if (tid < 128)
        atomicAdd(&rowsum[(size_t)bh * S_ + row0 + tid], red[tid * 2] + red[tid * 2 + 1]);

    float* Crow = scores + ((size_t)bh * S_ + row0) * S_ + col0;
#pragma unroll 1
    for (int i = 0; i < 16; i++) {
        int idx = i * 256 + tid;
        int rr = idx >> 5, c4 = (idx & 31) << 2;
        *(float4*)&Crow[(size_t)rr * S_ + c4] = *(float4*)&stg[rr * 132 + c4];
    }
}

// ---------------- normalize scores in place + PV (single-fp16 epilogue) ----------------
__global__ __launch_bounds__(256, 2) void mma_softmax_pv(
    float* __restrict__ scores, const float* __restrict__ rowsum,
    const h16* __restrict__ Vth, h16* __restrict__ attnh)
{
    extern __shared__ __align__(16) char smem[];
    const int tid = threadIdx.x, wid = tid >> 5, lane = tid & 31;
    const int bh = blockIdx.y;
    const int b = bh >> 4, hd = bh & 15;
    const int row0 = blockIdx.x * 128;

    float* rinv = (float*)(smem + AUX32);
    if (tid < 128) rinv[tid] = 1.0f / rowsum[(size_t)bh * S_ + row0 + tid];
    __syncthreads();

    float acc[2][8][4];
    ZERO_ACC(acc)
    gemm_core_pv(acc, scores + ((size_t)bh * S_ + row0) * S_, S_,
                 Vth + (size_t)b * HD_ * S_, S_, S_, smem, rinv);

    float* stg = (float*)smem;
    stage_acc(acc, stg, wid, lane);
    __syncthreads();
    h16* Cb = attnh + ((size_t)b * S_ + row0) * DM_ + hd * HD_;
#pragma unroll 1
    for (int i = 0; i < 16; i++) {
        int idx = i * 256 + tid;
        int rr = idx >> 5, c4 = (idx & 31) << 2;
        float4 v = *(float4*)&stg[rr * 132 + c4];
        uint32_t h0, h1; pack4h(v, h0, h1);
        *(uint2*)(Cb + (size_t)rr * DM_ + c4) = make_uint2(h0, h1);
    }
}

// ---------------- output GEMM (fp32 + bias epilogue) ----------------
__global__ __launch_bounds__(256, 2) void mma_out(
    const h16* __restrict__ Ag,
    const h16* __restrict__ Bg,
    const float* __restrict__ bias, float* __restrict__ C)
{
    extern __shared__ __align__(16) char smem[];
    const int tid = threadIdx.x, wid = tid >> 5, lane = tid & 31;
    const int row0 = blockIdx.y * 128, col0 = blockIdx.x * 128;

    float* bs = (float*)(smem + AUX64);
    if (tid < 128) bs[tid] = bias[col0 + tid];

    float acc[2][8][4];
    ZERO_ACC(acc)
    gemm_core_h(acc, Ag + (size_t)row0 * DM_, DM_,
                Bg + (size_t)col0 * DM_, DM_, DM_, smem);

    float* stg = (float*)smem;
    stage_acc(acc, stg, wid, lane);
    __syncthreads();
#pragma unroll 1
    for (int i = 0; i < 16; i++) {
        int idx = i * 256 + tid;
        int rr = idx >> 5, c4 = (idx & 31) << 2;
        float4 v = *(float4*)&stg[rr * 132 + c4];
        v.x += bs[c4]; v.y += bs[c4 + 1]; v.z += bs[c4 + 2]; v.w += bs[c4 + 3];
        *(float4*)&C[(size_t)(row0 + rr) * DM_ + col0 + c4] = v;
    }
}

// ---------------- launch ----------------
extern "C" void kernel_launch(void* const* d_in, const int* in_sizes, int n_in,
                              void* d_out, int out_size)
{
    const float* x  = (const float*)d_in[0];
    const float* Wq = (const float*)d_in[1];
    const float* bq = (const float*)d_in[2];
    const float* Wk = (const float*)d_in[3];
    const float* bk = (const float*)d_in[4];
    const float* Wv = (const float*)d_in[5];
    const float* bv = (const float*)d_in[6];
    const float* Wo = (const float*)d_in[7];
    const float* bo = (const float*)d_in[8];

    float* out = (float*)d_out;
    float* scores = out + (size_t)B_ * S_ * DM_;

    h16 *pxh, *pQh, *pKh, *pVth, *pAh;
    h16 *pWqh, *pWkh, *pWvh, *pWoh;
    float* pRS;
    cudaGetSymbolAddress((void**)&pxh, g_xh);
    cudaGetSymbolAddress((void**)&pQh, g_Qh);
    cudaGetSymbolAddress((void**)&pKh, g_Kh);
    cudaGetSymbolAddress((void**)&pVth, g_Vth);
    cudaGetSymbolAddress((void**)&pAh, g_attnh);
    cudaGetSymbolAddress((void**)&pWqh, g_Wqh);
    cudaGetSymbolAddress((void**)&pWkh, g_Wkh);
    cudaGetSymbolAddress((void**)&pWvh, g_Wvh);
    cudaGetSymbolAddress((void**)&pWoh, g_Woh);
    cudaGetSymbolAddress((void**)&pRS, g_rowsum);

    static int smem_set = 0;
    if (!smem_set) {
        cudaFuncSetAttribute(mma_qkvproj, cudaFuncAttributeMaxDynamicSharedMemorySize, SMEM64);
        cudaFuncSetAttribute(mma_scores, cudaFuncAttributeMaxDynamicSharedMemorySize, SMEM64);
        cudaFuncSetAttribute(mma_softmax_pv, cudaFuncAttributeMaxDynamicSharedMemorySize, SMEM32);
        cudaFuncSetAttribute(mma_out, cudaFuncAttributeMaxDynamicSharedMemorySize, SMEM64);
        smem_set = 1;
    }

    const int M = B_ * S_;   // 8192
    split_x_kernel<<<(M * DM_ / 4 + 255) / 256, 256>>>(x, pxh, M * DM_ / 4);
    transpose_pack_kernel<<<dim3(DM_ / 32, DM_ / 32), dim3(32, 8)>>>(Wq, pWqh, DM_, DM_);
    transpose_pack_kernel<<<dim3(HD_ / 32, DM_ / 32), dim3(32, 8)>>>(Wk, pWkh, DM_, HD_);
    transpose_pack_kernel<<<dim3(HD_ / 32, DM_ / 32), dim3(32, 8)>>>(Wv, pWvh, DM_, HD_);
    transpose_pack_kernel<<<dim3(DM_ / 32, DM_ / 32), dim3(32, 8)>>>(Wo, pWoh, DM_, DM_);
    zero_kernel<<<(B_ * H_ * S_ + 255) / 256, 256>>>(pRS, B_ * H_ * S_);

    mma_qkvproj<<<dim3(18, M / 128), 256, SMEM64>>>(
        pxh, pWqh, pWkh, pWvh, bq, bk, bv, pQh, pKh, pVth);

    mma_scores<<<dim3(S_ / 128, S_ / 128, B_ * H_), 256, SMEM64>>>(
        pQh, pKh, scores, pRS);
    mma_softmax_pv<<<dim3(S_ / 128, B_ * H_), 256, SMEM32>>>(
        scores, pRS, pVth, pAh);

    mma_out<<<dim3(DM_ / 128, M / 128), 256, SMEM64>>>(pAh, pWoh, bo, out);
}

// round 17
// speedup vs baseline: 1.1060x; 1.1044x over previous
#include <cuda_runtime.h>
#include <cuda_fp16.h>
#include <cstdint>

// Problem dims
#define B_  4
#define S_  2048
#define DM_ 2048
#define H_  16
#define HD_ 128
#define SCALE_ 0.08838834764831843f   // 1/sqrt(128)

typedef __half h16;

// ---------------- scratch (__device__ globals) ----------------
__device__ h16 g_xh[(size_t)B_ * S_ * DM_];       // single fp16
__device__ h16 g_Qh[(size_t)B_ * S_ * DM_];
__device__ h16 g_Kh[(size_t)B_ * S_ * HD_];
__device__ h16 g_Vth[(size_t)B_ * HD_ * S_];      // [B][128][2048]
__device__ h16 g_attnh[(size_t)B_ * S_ * DM_];
__device__ h16 g_Wqh[(size_t)DM_ * DM_];          // transposed [N][K]
__device__ h16 g_Wkh[(size_t)HD_ * DM_];
__device__ h16 g_Wvh[(size_t)HD_ * DM_];
__device__ h16 g_Woh[(size_t)DM_ * DM_];
__device__ float g_rowsum[(size_t)B_ * H_ * S_];

// ---------------- smem layouts (R12-proven) ----------------
// BK=64 cores: 2-stage; stage = {A, B}, each 128 x 72 fp16 = 18432 B
#define LDT64   72
#define TILE64  (128 * LDT64 * 2)         // 18432
#define STAGE64 (2 * TILE64)              // 36864
#define AUX64   73728                     // after 2 stages; fp32 staging 67584 unions below
#define RED64   (AUX64 + 512)
#define SMEM64  (AUX64 + 1536)            // 75264
// BK=32 PV core: 2-stage; stage = {A, B}, each 128 x 40 fp16 = 10240 B
#define LDT32   40
#define TILE32  10240
#define STAGE32 (2 * TILE32)              // 20480
#define AUX32   67584                     // after fp32 staging 128x132x4
#define SMEM32  69632

// ---------------- low-level helpers ----------------
__device__ __forceinline__ uint32_t smem_u32(const void* p) {
    uint32_t a;
    asm("{ .reg .u64 t; cvta.to.shared.u64 t, %1; cvt.u32.u64 %0, t; }" : "=r"(a) : "l"(p));
    return a;
}
__device__ __forceinline__ void cp16(uint32_t s, const void* g) {
    asm volatile("cp.async.ca.shared.global [%0], [%1], 16;"
                 :: "r"(s), "l"(__cvta_generic_to_global(g)));
}
#define CP_COMMIT() asm volatile("cp.async.commit_group;" ::: "memory")
#define CP_WAIT1()  asm volatile("cp.async.wait_group 1;" ::: "memory")
__device__ __forceinline__ void ldsm4(uint32_t* r, uint32_t a) {
    asm volatile("ldmatrix.sync.aligned.m8n8.x4.shared.b16 {%0,%1,%2,%3}, [%4];"
        : "=r"(r[0]), "=r"(r[1]), "=r"(r[2]), "=r"(r[3]) : "r"(a));
}
__device__ __forceinline__ void mma_fp16(float* d, const uint32_t* a, uint32_t b0, uint32_t b1) {
    asm volatile("mma.sync.aligned.m16n8k16.row.col.f32.f16.f16.f32 "
        "{%0,%1,%2,%3}, {%4,%5,%6,%7}, {%8,%9}, {%0,%1,%2,%3};"
        : "+f"(d[0]), "+f"(d[1]), "+f"(d[2]), "+f"(d[3])
        : "r"(a[0]), "r"(a[1]), "r"(a[2]), "r"(a[3]), "r"(b0), "r"(b1));
}
__device__ __forceinline__ uint32_t hbits2(__half2 h) {
    return *reinterpret_cast<uint32_t*>(&h);
}
__device__ __forceinline__ void pack4h(float4 v, uint32_t& h0, uint32_t& h1) {
    __half2 a = __floats2half2_rn(v.x, v.y);
    __half2 b = __floats2half2_rn(v.z, v.w);
    h0 = hbits2(a); h1 = hbits2(b);
}

// ---------------- BK=64 tile movement ----------------
__device__ __forceinline__ void issue_tiles64(char* buf,
    const h16* __restrict__ Ag, size_t lda,
    const h16* __restrict__ Bg, size_t ldb,
    int k0, int tid)
{
    uint32_t sA = smem_u32(buf);
#pragma unroll
    for (int i = 0; i < 4; i++) {
        int idx = i * 256 + tid;              // 0..1023
        int r = idx >> 3, c8 = (idx & 7) * 8;
        cp16(sA + r * (LDT64 * 2) + c8 * 2, Ag + (size_t)r * lda + k0 + c8);
    }
    uint32_t sB = sA + TILE64;
#pragma unroll
    for (int i = 0; i < 4; i++) {
        int idx = i * 256 + tid;
        int r = idx >> 3, c8 = (idx & 7) * 8;
        cp16(sB + r * (LDT64 * 2) + c8 * 2, Bg + (size_t)r * ldb + k0 + c8);
    }
}
// BK=32 B-only (PV)
__device__ __forceinline__ void issue_B32(char* buf,
    const h16* __restrict__ Bg, size_t ldb, int k0, int tid)
{
    uint32_t sB = smem_u32(buf) + TILE32;
#pragma unroll
    for (int i = 0; i < 2; i++) {
        int idx = i * 256 + tid;
        int r = idx >> 2, c8 = (idx & 3) * 8;
        cp16(sB + r * (LDT32 * 2) + c8 * 2, Bg + (size_t)r * ldb + k0 + c8);
    }
}

// ---------------- MMA compute: one chunk, warp 32x64, 1-term ----------------
template<int LDT, int TILE, int BK>
__device__ __forceinline__ void compute_chunk(float (*acc)[8][4], char* buf,
                                              int wm, int wn, int lane)
{
    h16* Ah = (h16*)buf;
    h16* Bh = (h16*)(buf + TILE);
    const int ar = lane & 15;
    const int acs = (lane >> 4) << 3;
#pragma unroll
    for (int kk = 0; kk < BK; kk += 16) {
        const int ac = kk + acs;
        uint32_t aH[2][4];
#pragma unroll
        for (int mt = 0; mt < 2; mt++)
            ldsm4(aH[mt], smem_u32(Ah + (wm * 32 + mt * 16 + ar) * LDT + ac));
#pragma unroll
        for (int p = 0; p < 4; p++) {
            uint32_t bh[4];
            ldsm4(bh, smem_u32(Bh + (wn * 64 + p * 16 + ar) * LDT + ac));
#pragma unroll
            for (int mt = 0; mt < 2; mt++) {
                mma_fp16(acc[mt][2 * p],     aH[mt], bh[0], bh[2]);
                mma_fp16(acc[mt][2 * p + 1], aH[mt], bh[1], bh[3]);
            }
        }
    }
}

// BK=64 pipelined core (R12 structure: 2-stage, two syncs per chunk)
__device__ __forceinline__ void gemm_core_h(float (*acc)[8][4],
    const h16* __restrict__ Ag, size_t lda,
    const h16* __restrict__ Bg, size_t ldb,
    int Kdim, char* smem)
{
    const int tid = threadIdx.x, wid = tid >> 5, lane = tid & 31;
    const int wm = wid & 3, wn = wid >> 2;
    const int nC = Kdim >> 6;
    issue_tiles64(smem, Ag, lda, Bg, ldb, 0, tid); CP_COMMIT();
    issue_tiles64(smem + STAGE64, Ag, lda, Bg, ldb, 64, tid); CP_COMMIT();
#pragma unroll 1
    for (int c = 0; c < nC; c++) {
        char* buf = smem + (c & 1) * STAGE64;
        CP_WAIT1();
        __syncthreads();
        compute_chunk<LDT64, TILE64, 64>(acc, buf, wm, wn, lane);
        __syncthreads();
        if (c + 2 < nC)
            issue_tiles64(buf, Ag, lda, Bg, ldb, (c + 2) * 64, tid);
        CP_COMMIT();
    }
    asm volatile("cp.async.wait_all;" ::: "memory");
    __syncthreads();
}

// PV core (R12 structure): BK=32, 2-stage, A = fp32 scores with register
// double-buffer prefetch: normalize by rinv, write back, pack fp16 to smem.
__device__ __forceinline__ void gemm_core_pv(float (*acc)[8][4],
    float* __restrict__ A, size_t lda,
    const h16* __restrict__ Bg, size_t ldb,
    int Kdim, char* smem, const float* __restrict__ rinv)
{
    const int tid = threadIdx.x, wid = tid >> 5, lane = tid & 31;
    const int wm = wid & 3, wn = wid >> 2;
    const int nC = Kdim >> 5;                     // 64
    issue_B32(smem, Bg, ldb, 0, tid); CP_COMMIT();
    issue_B32(smem + STAGE32, Bg, ldb, 32, tid); CP_COMMIT();

    float4 pr[4];
#pragma unroll
    for (int i = 0; i < 4; i++) {
        int idx = i * 256 + tid;
        int rr = idx >> 3, cc = (idx & 7) * 4;
        pr[i] = *(const float4*)(A + (size_t)rr * lda + cc);
    }
#pragma unroll 1
    for (int c = 0; c < nC; c++) {
        char* buf = smem + (c & 1) * STAGE32;
        CP_WAIT1();
        h16* Ah = (h16*)buf;
#pragma unroll
        for (int i = 0; i < 4; i++) {
            int idx = i * 256 + tid;
            int rr = idx >> 3, cc = (idx & 7) * 4;
            float ri = rinv[rr];
            float4 v = pr[i];
            v.x *= ri; v.y *= ri; v.z *= ri; v.w *= ri;
            *(float4*)(A + (size_t)rr * lda + c * 32 + cc) = v;
            uint32_t h0, h1; pack4h(v, h0, h1);
            *(uint2*)(Ah + rr * LDT32 + cc) = make_uint2(h0, h1);
        }
        if (c + 1 < nC) {
#pragma unroll
            for (int i = 0; i < 4; i++) {
                int idx = i * 256 + tid;
                int rr = idx >> 3, cc = (idx & 7) * 4;
                pr[i] = *(const float4*)(A + (size_t)rr * lda + (c + 1) * 32 + cc);
            }
        }
        __syncthreads();
        compute_chunk<LDT32, TILE32, 32>(acc, buf, wm, wn, lane);
        __syncthreads();
        if (c + 2 < nC)
            issue_B32(buf, Bg, ldb, (c + 2) * 32, tid);
        CP_COMMIT();
    }
    asm volatile("cp.async.wait_all;" ::: "memory");
    __syncthreads();
}

// stage acc (fp32) into smem [128][132]
__device__ __forceinline__ void stage_acc(float (*acc)[8][4], float* stg, int wid, int lane) {
    int wm = wid & 3, wn = wid >> 2;
    int r0 = wm * 32 + (lane >> 2), c0 = wn * 64 + (lane & 3) * 2;
#pragma unroll
    for (int mt = 0; mt < 2; mt++)
#pragma unroll
        for (int nt = 0; nt < 8; nt++) {
            int r = r0 + mt * 16, c = c0 + nt * 8;
            *(float2*)&stg[r * 132 + c] = make_float2(acc[mt][nt][0], acc[mt][nt][1]);
            *(float2*)&stg[(r + 8) * 132 + c] = make_float2(acc[mt][nt][2], acc[mt][nt][3]);
        }
}

#define ZERO_ACC(acc) \
    _Pragma("unroll") for (int i_ = 0; i_ < 2; i_++) \
    _Pragma("unroll") for (int j_ = 0; j_ < 8; j_++) \
    _Pragma("unroll") for (int q_ = 0; q_ < 4; q_++) acc[i_][j_][q_] = 0.0f;

// ---------------- prep kernels ----------------
__global__ void split_x_kernel(const float* __restrict__ x, h16* __restrict__ xh, int n4) {
    int i = blockIdx.x * blockDim.x + threadIdx.x;
    if (i >= n4) return;
    float4 v = *(const float4*)(x + 4 * (size_t)i);
    uint32_t h0, h1; pack4h(v, h0, h1);
    *(uint2*)(xh + 4 * (size_t)i) = make_uint2(h0, h1);
}
// Fused transpose+pack of all four weights: flat x segments
// [0,64) Wq | [64,128) Wo | [128,132) Wk | [132,136) Wv. M (rows of src) = 2048 always.
__global__ void transpose_pack_all(
    const float* __restrict__ Wq, const float* __restrict__ Wo,
    const float* __restrict__ Wk, const float* __restrict__ Wv,
    h16* __restrict__ dWq, h16* __restrict__ dWo,
    h16* __restrict__ dWk, h16* __restrict__ dWv)
{
    __shared__ float t[32][33];
    int fx = blockIdx.x;
    const float* src; h16* dst; int N; int lbx;
    if (fx < 64)       { src = Wq; dst = dWq; N = DM_; lbx = fx; }
    else if (fx < 128) { src = Wo; dst = dWo; N = DM_; lbx = fx - 64; }
    else if (fx < 132) { src = Wk; dst = dWk; N = HD_; lbx = fx - 128; }
    else               { src = Wv; dst = dWv; N = HD_; lbx = fx - 132; }
    int bx = lbx * 32, by = blockIdx.y * 32;
    int x = threadIdx.x, y0 = threadIdx.y;
#pragma unroll
    for (int j = 0; j < 32; j += 8)
        t[y0 + j][x] = src[(size_t)(by + y0 + j) * N + bx + x];
    __syncthreads();
#pragma unroll
    for (int j = 0; j < 32; j += 8)
        dst[(size_t)(bx + y0 + j) * DM_ + by + x] = __float2half_rn(t[x][y0 + j]);
}
__global__ void zero_kernel(float* p, int n) {
    int i = blockIdx.x * blockDim.x + threadIdx.x;
    if (i < n) p[i] = 0.0f;
}

// ---------------- fused Q + K + V projection ----------------
// grid (18, 64): x<16 -> Q col tile x; x==16 -> K; x==17 -> V
__global__ __launch_bounds__(256, 2) void mma_qkvproj(
    const h16* __restrict__ Ag,
    const h16* __restrict__ Wqh, const h16* __restrict__ Wkh, const h16* __restrict__ Wvh,
    const float* __restrict__ bq, const float* __restrict__ bk, const float* __restrict__ bv,
    h16* __restrict__ Qh, h16* __restrict__ Kh, h16* __restrict__ Vth)
{
    extern __shared__ __align__(16) char smem[];
    const int tid = threadIdx.x, wid = tid >> 5, lane = tid & 31;
    const int bx = blockIdx.x;
    const int row0 = blockIdx.y * 128;

    const h16* Bg;
    const float* bias;
    if (bx < 16)      { Bg = Wqh + (size_t)bx * 128 * DM_; bias = bq + bx * 128; }
    else if (bx == 16){ Bg = Wkh; bias = bk; }
    else              { Bg = Wvh; bias = bv; }

    float* bs = (float*)(smem + AUX64);
    if (tid < 128) bs[tid] = bias[tid];

    float acc[2][8][4];
    ZERO_ACC(acc)
    gemm_core_h(acc, Ag + (size_t)row0 * DM_, DM_, Bg, DM_, DM_, smem);

    float* stg = (float*)smem;
    stage_acc(acc, stg, wid, lane);
    __syncthreads();
    if (bx < 16) {
#pragma unroll 1
        for (int i = 0; i < 16; i++) {
            int idx = i * 256 + tid;
            int rr = idx >> 5, c4 = (idx & 31) << 2;
            float4 v = *(float4*)&stg[rr * 132 + c4];
            v.x += bs[c4]; v.y += bs[c4 + 1]; v.z += bs[c4 + 2]; v.w += bs[c4 + 3];
            uint32_t h0, h1; pack4h(v, h0, h1);
            *(uint2*)(Qh + (size_t)(row0 + rr) * DM_ + bx * 128 + c4) = make_uint2(h0, h1);
        }
    } else if (bx == 16) {
#pragma unroll 1
        for (int i = 0; i < 16; i++) {
            int idx = i * 256 + tid;
            int rr = idx >> 5, c4 = (idx & 31) << 2;
            float4 v = *(float4*)&stg[rr * 132 + c4];
            v.x += bs[c4]; v.y += bs[c4 + 1]; v.z += bs[c4 + 2]; v.w += bs[c4 + 3];
            uint32_t h0, h1; pack4h(v, h0, h1);
            *(uint2*)(Kh + (size_t)(row0 + rr) * HD_ + c4) = make_uint2(h0, h1);
        }
    } else {
        int b = row0 >> 11;
        int s0 = row0 & (S_ - 1);
        h16* Vb = Vth + (size_t)b * HD_ * S_;
#pragma unroll 1
        for (int i = 0; i < 64; i++) {
            int idx = i * 256 + tid;
            int m = idx & 127, n = idx >> 7;
            Vb[(size_t)n * S_ + s0 + m] = __float2half_rn(stg[m * 132 + n] + bs[n]);
        }
    }
}

// ---------------- scores: E = exp(scale * Q Kt) fp32 out + rowsums ----------------
__global__ __launch_bounds__(256, 2) void mma_scores(
    const h16* __restrict__ Qh,
    const h16* __restrict__ Kh,
    float* __restrict__ scores, float* __restrict__ rowsum)
{
    extern __shared__ __align__(16) char smem[];
    const int tid = threadIdx.x, wid = tid >> 5, lane = tid & 31;
    const int bh = blockIdx.z;
    const int b = bh >> 4, hd = bh & 15;
    const int row0 = blockIdx.y * 128, col0 = blockIdx.x * 128;

    float acc[2][8][4];
    ZERO_ACC(acc)
    gemm_core_h(acc,
        Qh + ((size_t)b * S_ + row0) * DM_ + hd * HD_, DM_,
        Kh + ((size_t)b * S_ + col0) * HD_, HD_, HD_, smem);

    float* stg = (float*)smem;
    float* red = (float*)(smem + RED64);
    const int wm = wid & 3, wn = wid >> 2;
    const int r0 = wm * 32 + (lane >> 2), c0 = wn * 64 + (lane & 3) * 2;
    float sums[2][2] = {{0.f, 0.f}, {0.f, 0.f}};
#pragma unroll
    for (int mt = 0; mt < 2; mt++)
#pragma unroll
        for (int nt = 0; nt < 8; nt++) {
            float e0 = __expf(acc[mt][nt][0] * SCALE_);
            float e1 = __expf(acc[mt][nt][1] * SCALE_);
            float e2 = __expf(acc[mt][nt][2] * SCALE_);
            float e3 = __expf(acc[mt][nt][3] * SCALE_);
            int r = r0 + mt * 16, c = c0 + nt * 8;
            *(float2*)&stg[r * 132 + c] = make_float2(e0, e1);
            *(float2*)&stg[(r + 8) * 132 + c] = make_float2(e2, e3);
            sums[mt][0] += e0 + e1;
            sums[mt][1] += e2 + e3;
        }
#pragma unroll
    for (int mt = 0; mt < 2; mt++)
#pragma unroll
        for (int hh = 0; hh < 2; hh++) {
            float v = sums[mt][hh];
            v += __shfl_xor_sync(0xFFFFFFFFu, v, 1);
            v += __shfl_xor_sync(0xFFFFFFFFu, v, 2);
            sums[mt][hh] = v;
        }
    if ((lane & 3) == 0) {
#pragma unroll
        for (int mt = 0; mt < 2; mt++)
#pragma unroll
            for (int hh = 0; hh < 2; hh++)
                red[(wm * 32 + mt * 16 + hh * 8 + (lane >> 2)) * 2 + wn] = sums[mt][hh];
    }
    __syncthreads();
    if (tid < 128)
        atomicAdd(&rowsum[(size_t)bh * S_ + row0 + tid], red[tid * 2] + red[tid * 2 + 1]);

    float* Crow = scores + ((size_t)bh * S_ + row0) * S_ + col0;
#pragma unroll 1
    for (int i = 0; i < 16; i++) {
        int idx = i * 256 + tid;
        int rr = idx >> 5, c4 = (idx & 31) << 2;
        *(float4*)&Crow[(size_t)rr * S_ + c4] = *(float4*)&stg[rr * 132 + c4];
    }
}

// ---------------- normalize scores in place + PV (single-fp16 epilogue) ----------------
__global__ __launch_bounds__(256, 2) void mma_softmax_pv(
    float* __restrict__ scores, const float* __restrict__ rowsum,
    const h16* __restrict__ Vth, h16* __restrict__ attnh)
{
    extern __shared__ __align__(16) char smem[];
    const int tid = threadIdx.x, wid = tid >> 5, lane = tid & 31;
    const int bh = blockIdx.y;
    const int b = bh >> 4, hd = bh & 15;
    const int row0 = blockIdx.x * 128;

    float* rinv = (float*)(smem + AUX32);
    if (tid < 128) rinv[tid] = 1.0f / rowsum[(size_t)bh * S_ + row0 + tid];
    __syncthreads();

    float acc[2][8][4];
    ZERO_ACC(acc)
    gemm_core_pv(acc, scores + ((size_t)bh * S_ + row0) * S_, S_,
                 Vth + (size_t)b * HD_ * S_, S_, S_, smem, rinv);

    float* stg = (float*)smem;
    stage_acc(acc, stg, wid, lane);
    __syncthreads();
    h16* Cb = attnh + ((size_t)b * S_ + row0) * DM_ + hd * HD_;
#pragma unroll 1
    for (int i = 0; i < 16; i++) {
        int idx = i * 256 + tid;
        int rr = idx >> 5, c4 = (idx & 31) << 2;
        float4 v = *(float4*)&stg[rr * 132 + c4];
        uint32_t h0, h1; pack4h(v, h0, h1);
        *(uint2*)(Cb + (size_t)rr * DM_ + c4) = make_uint2(h0, h1);
    }
}

// ---------------- output GEMM (fp32 + bias epilogue) ----------------
__global__ __launch_bounds__(256, 2) void mma_out(
    const h16* __restrict__ Ag,
    const h16* __restrict__ Bg,
    const float* __restrict__ bias, float* __restrict__ C)
{
    extern __shared__ __align__(16) char smem[];
    const int tid = threadIdx.x, wid = tid >> 5, lane = tid & 31;
    const int row0 = blockIdx.y * 128, col0 = blockIdx.x * 128;

    float* bs = (float*)(smem + AUX64);
    if (tid < 128) bs[tid] = bias[col0 + tid];

    float acc[2][8][4];
    ZERO_ACC(acc)
    gemm_core_h(acc, Ag + (size_t)row0 * DM_, DM_,
                Bg + (size_t)col0 * DM_, DM_, DM_, smem);

    float* stg = (float*)smem;
    stage_acc(acc, stg, wid, lane);
    __syncthreads();
#pragma unroll 1
    for (int i = 0; i < 16; i++) {
        int idx = i * 256 + tid;
        int rr = idx >> 5, c4 = (idx & 31) << 2;
        float4 v = *(float4*)&stg[rr * 132 + c4];
        v.x += bs[c4]; v.y += bs[c4 + 1]; v.z += bs[c4 + 2]; v.w += bs[c4 + 3];
        *(float4*)&C[(size_t)(row0 + rr) * DM_ + col0 + c4] = v;
    }
}

// ---------------- launch ----------------
extern "C" void kernel_launch(void* const* d_in, const int* in_sizes, int n_in,
                              void* d_out, int out_size)
{
    const float* x  = (const float*)d_in[0];
    const float* Wq = (const float*)d_in[1];
    const float* bq = (const float*)d_in[2];
    const float* Wk = (const float*)d_in[3];
    const float* bk = (const float*)d_in[4];
    const float* Wv = (const float*)d_in[5];
    const float* bv = (const float*)d_in[6];
    const float* Wo = (const float*)d_in[7];
    const float* bo = (const float*)d_in[8];

    float* out = (float*)d_out;
    float* scores = out + (size_t)B_ * S_ * DM_;

    h16 *pxh, *pQh, *pKh, *pVth, *pAh;
    h16 *pWqh, *pWkh, *pWvh, *pWoh;
    float* pRS;
    cudaGetSymbolAddress((void**)&pxh, g_xh);
    cudaGetSymbolAddress((void**)&pQh, g_Qh);
    cudaGetSymbolAddress((void**)&pKh, g_Kh);
    cudaGetSymbolAddress((void**)&pVth, g_Vth);
    cudaGetSymbolAddress((void**)&pAh, g_attnh);
    cudaGetSymbolAddress((void**)&pWqh, g_Wqh);
    cudaGetSymbolAddress((void**)&pWkh, g_Wkh);
    cudaGetSymbolAddress((void**)&pWvh, g_Wvh);
    cudaGetSymbolAddress((void**)&pWoh, g_Woh);
    cudaGetSymbolAddress((void**)&pRS, g_rowsum);

    static int smem_set = 0;
    if (!smem_set) {
        cudaFuncSetAttribute(mma_qkvproj, cudaFuncAttributeMaxDynamicSharedMemorySize, SMEM64);
        cudaFuncSetAttribute(mma_scores, cudaFuncAttributeMaxDynamicSharedMemorySize, SMEM64);
        cudaFuncSetAttribute(mma_softmax_pv, cudaFuncAttributeMaxDynamicSharedMemorySize, SMEM32);
        cudaFuncSetAttribute(mma_out, cudaFuncAttributeMaxDynamicSharedMemorySize, SMEM64);
        smem_set = 1;
    }

    const int M = B_ * S_;   // 8192
    split_x_kernel<<<(M * DM_ / 4 + 255) / 256, 256>>>(x, pxh, M * DM_ / 4);
    transpose_pack_all<<<dim3(136, 64), dim3(32, 8)>>>(
        Wq, Wo, Wk, Wv, pWqh, pWoh, pWkh, pWvh);
    zero_kernel<<<(B_ * H_ * S_ + 255) / 256, 256>>>(pRS, B_ * H_ * S_);

    mma_qkvproj<<<dim3(18, M / 128), 256, SMEM64>>>(
        pxh, pWqh, pWkh, pWvh, bq, bk, bv, pQh, pKh, pVth);

    mma_scores<<<dim3(S_ / 128, S_ / 128, B_ * H_), 256, SMEM64>>>(
        pQh, pKh, scores, pRS);
    mma_softmax_pv<<<dim3(S_ / 128, B_ * H_), 256, SMEM32>>>(
        scores, pRS, pVth, pAh);

    mma_out<<<dim3(DM_ / 128, M / 128), 256, SMEM64>>>(pAh, pWoh, bo, out);
}